// round 6
// baseline (speedup 1.0000x reference)
#include <cuda_runtime.h>
#include <cuda_fp16.h>
#include <cstdint>

#define BB 4
#define CI 256
#define CO 256
#define HH 64
#define WW 64
#define HW 4096
#define KD 2304          // CI * 9
#define MTOT 16384
#define KC 32
#define NCHUNK 72        // KD / KC

// ---------------- scratch ----------------
__device__ float g_poff[4 * BB * 18 * HW];
__device__ float g_off[BB * 18 * HW];
__device__ __align__(16) uint32_t g_wB[NCHUNK * 4096];     // frag-ordered fp16 B
__device__ __align__(16) uint32_t g_A[288 * MTOT * 4];     // sampled A fp16, [kchunk][m][8k]
__device__ __align__(16) float g_raw[BB * CO * HW];
__device__ float g_scale[CO];
__device__ float g_shift[CO];

// ---------------- helpers ----------------
__device__ __forceinline__ uint32_t smem_u32(const void* p) {
    uint32_t a;
    asm("{ .reg .u64 t; cvta.to.shared.u64 t, %1; cvt.u32.u64 %0, t; }" : "=r"(a) : "l"(p));
    return a;
}
__device__ __forceinline__ uint32_t pack_h2(float lo, float hi) {
    __half2 h = __floats2half2_rn(lo, hi);
    return *(uint32_t*)&h;
}
__device__ __forceinline__ void mma_f16(float* d, const uint32_t* a,
                                        uint32_t b0, uint32_t b1) {
    asm volatile(
        "mma.sync.aligned.m16n8k16.row.col.f32.f16.f16.f32 "
        "{%0,%1,%2,%3}, {%4,%5,%6,%7}, {%8,%9}, {%0,%1,%2,%3};"
        : "+f"(d[0]), "+f"(d[1]), "+f"(d[2]), "+f"(d[3])
        : "r"(a[0]), "r"(a[1]), "r"(a[2]), "r"(a[3]), "r"(b0), "r"(b1));
}
__device__ __forceinline__ void cp_async16(uint32_t saddr, const void* gaddr) {
    asm volatile("cp.async.cg.shared.global [%0], [%1], 16;" :: "r"(saddr), "l"(gaddr));
}

// ---------------- kernel: pack B into fragment order (fp16) ---------------
__global__ void prep_wB(const float* __restrict__ w_conv) {
    int idx = blockIdx.x * 256 + threadIdx.x;
    if (idx >= NCHUNK * 4096) return;
    int kt = idx >> 12;
    int r  = idx & 4095;
    int k16  = r >> 11;
    int np   = (r >> 7) & 15;
    int lane = (r >> 2) & 31;
    int w    = r & 3;
    int g = lane >> 2, tg = lane & 3;
    int nt = np * 2 + (w >> 1);
    int h  = w & 1;
    int n  = nt * 8 + g;
    int ck = kt * KC + k16 * 16 + h * 8 + 2 * tg;
    g_wB[idx] = pack_h2(w_conv[n * KD + ck], w_conv[n * KD + ck + 1]);
}

// ---------------- offset conv partials -------------------------------------
__global__ void offset_partial(const float* __restrict__ x,
                               const float* __restrict__ w_off) {
    __shared__ __align__(16) float ws[8 * 164];
    int b  = blockIdx.x >> 4;
    int hq = blockIdx.x & 15;
    int cq = blockIdx.y;
    int tid = threadIdx.x;
    int h = hq * 4 + (tid >> 6);
    int w = tid & 63;

    unsigned long long acc2[9];
#pragma unroll
    for (int p = 0; p < 9; p++) acc2[p] = 0ULL;

    const float* xb = x + (size_t)b * CI * HW;

    for (int cc = 0; cc < 64; cc += 8) {
        int c0 = cq * 64 + cc;
        for (int e = tid; e < 8 * 162; e += 256) {
            int ci = e / 162;
            int r  = e - ci * 162;
            int j  = r / 18;
            int o  = r - j * 18;
            ws[ci * 164 + j * 18 + o] = w_off[o * KD + (c0 + ci) * 9 + j];
        }
        __syncthreads();

        for (int ci = 0; ci < 8; ci++) {
            const float* xc = xb + (c0 + ci) * HW;
            float v[9];
#pragma unroll
            for (int ki = 0; ki < 3; ki++) {
                int yy = h + ki - 1;
                bool vy = (yy >= 0 && yy < HH);
#pragma unroll
                for (int kj = 0; kj < 3; kj++) {
                    int xx = w + kj - 1;
                    v[ki * 3 + kj] = (vy && xx >= 0 && xx < WW) ? xc[yy * WW + xx] : 0.f;
                }
            }
#pragma unroll
            for (int j = 0; j < 9; j++) {
                unsigned long long a2;
                asm("mov.b64 %0, {%1, %1};" : "=l"(a2) : "r"(__float_as_uint(v[j])));
                const unsigned long long* ww2 =
                    (const unsigned long long*)(ws + ci * 164 + j * 18);
#pragma unroll
                for (int p = 0; p < 9; p++)
                    asm("fma.rn.f32x2 %0, %1, %2, %0;"
                        : "+l"(acc2[p]) : "l"(a2), "l"(ww2[p]));
            }
        }
        __syncthreads();
    }
#pragma unroll
    for (int p = 0; p < 9; p++) {
        unsigned int ul, uh;
        asm("mov.b64 {%0, %1}, %2;" : "=r"(ul), "=r"(uh) : "l"(acc2[p]));
        g_poff[((cq * 4 + b) * 18 + 2 * p)     * HW + h * WW + w] = __uint_as_float(ul);
        g_poff[((cq * 4 + b) * 18 + 2 * p + 1) * HW + h * WW + w] = __uint_as_float(uh);
    }
}

__global__ void offset_reduce(const float* __restrict__ b_off) {
    int idx = blockIdx.x * 256 + threadIdx.x;
    if (idx >= BB * 18 * HW) return;
    int hw = idx & 4095;
    int bo = idx >> 12;
    int b = bo / 18;
    int o = bo - b * 18;
    float s = b_off[o];
#pragma unroll
    for (int cq = 0; cq < 4; cq++)
        s += g_poff[((cq * 4 + b) * 18 + o) * HW + hw];
    g_off[idx] = s;
}

// ---------------- kernel: deformable gather -> fp16 A ---------------------
// grid (128 m-groups, 9 k-groups), block 256.  A layout: [kchunk(288)][m(16384)][8k fp16]
__global__ void __launch_bounds__(256) gather_A_kernel(const float* __restrict__ x) {
    __shared__ __align__(16) ushort4 gidx[9 * 128];
    __shared__ __align__(16) float4  gwts[9 * 128];
    const int tid = threadIdx.x;
    const int m0 = blockIdx.x << 7;
    const int b  = m0 >> 12;
    const float* xb = x + (size_t)b * CI * HW;

    for (int e = tid; e < 9 * 128; e += 256) {
        int k  = e >> 7;
        int mm = e & 127;
        int hw = (m0 + mm) & 4095;
        int h  = hw >> 6;
        int w  = hw & 63;
        float offy = g_off[(b * 18 + 2 * k) * HW + hw];
        float offx = g_off[(b * 18 + 2 * k + 1) * HW + hw];
        int k3 = k / 3;
        float py = (float)(h + k3 - 1) + offy;
        float px = (float)(w + (k - k3 * 3) - 1) + offx;
        float fy0 = floorf(py), fx0 = floorf(px);
        float wy1 = py - fy0, wx1 = px - fx0;
        float wy0 = 1.f - wy1, wx0 = 1.f - wx1;
        int iy0 = (int)fy0, ix0 = (int)fx0;
        int iy1 = iy0 + 1, ix1 = ix0 + 1;
        float vy0 = (iy0 >= 0 && iy0 < HH) ? 1.f : 0.f;
        float vy1 = (iy1 >= 0 && iy1 < HH) ? 1.f : 0.f;
        float vx0 = (ix0 >= 0 && ix0 < WW) ? 1.f : 0.f;
        float vx1 = (ix1 >= 0 && ix1 < WW) ? 1.f : 0.f;
        int cy0 = min(max(iy0, 0), HH - 1), cy1 = min(max(iy1, 0), HH - 1);
        int cx0 = min(max(ix0, 0), WW - 1), cx1 = min(max(ix1, 0), WW - 1);
        ushort4 gi;
        gi.x = (unsigned short)(cy0 * WW + cx0);
        gi.y = (unsigned short)(cy0 * WW + cx1);
        gi.z = (unsigned short)(cy1 * WW + cx0);
        gi.w = (unsigned short)(cy1 * WW + cx1);
        gidx[e] = gi;
        gwts[e] = make_float4(wy0 * wx0 * vy0 * vx0,
                              wy0 * wx1 * vy0 * vx1,
                              wy1 * wx0 * vy1 * vx0,
                              wy1 * wx1 * vy1 * vx1);
    }
    __syncthreads();

    const int mm = tid & 127;       // warp = 32 consecutive pixels
    const int ch = tid >> 7;        // chunk parity
    const int kb0 = blockIdx.y * 256;

#pragma unroll 1
    for (int it = 0; it < 16; it++) {
        int kc_in = ch + it * 2;            // chunk within block, 0..31
        int ckb = kb0 + kc_in * 8;
        float v[8];
#pragma unroll
        for (int s = 0; s < 8; s++) {
            int ck = ckb + s;
            int c = ck / 9;
            int tap = ck - c * 9;
            ushort4 gi = gidx[tap * 128 + mm];
            float4  gw = gwts[tap * 128 + mm];
            const float* xc = xb + (c << 12);
            v[s] = gw.x * __ldg(xc + gi.x) + gw.y * __ldg(xc + gi.y)
                 + gw.z * __ldg(xc + gi.z) + gw.w * __ldg(xc + gi.w);
        }
        uint4 wv;
        wv.x = pack_h2(v[0], v[1]);
        wv.y = pack_h2(v[2], v[3]);
        wv.z = pack_h2(v[4], v[5]);
        wv.w = pack_h2(v[6], v[7]);
        int kc = (kb0 >> 3) + kc_in;
        *(uint4*)(g_A + ((size_t)kc * MTOT + m0 + mm) * 4) = wv;
    }
}

// ---------------- kernel: pipelined fp16 HMMA GEMM -------------------------
// 128(m) x 256(n) tile, 512 thr, 16 warps (4x4), KC=32, 3-stage cp.async.
#define ST_A 8192
#define ST_B 16384
#define OFF_A 0
#define OFF_B (3 * ST_A)
#define SMEM_GEMM (3 * ST_A + 3 * ST_B)     // 73728

__global__ void __launch_bounds__(512, 1)
gemm_main(int dummy) {
    extern __shared__ char smem[];
    const uint32_t sb = smem_u32(smem);
    const int tid  = threadIdx.x;
    const int lane = tid & 31;
    const int wid  = tid >> 5;
    const int g  = lane >> 2;
    const int tg = lane & 3;
    const int wm = wid & 3;
    const int wn = wid >> 2;
    const int m0 = blockIdx.x << 7;
    const int b  = m0 >> 12;

    // cp.async thread mapping for A: (kcl, m)
    const int cm  = tid & 127;
    const int ckl = tid >> 7;       // 0..3
    const uint32_t dstA_off = (uint32_t)((cm >> 1) * 128
                          + (((((cm & 1) << 2) + ckl) ^ ((cm >> 1) & 7)) << 4));

    auto issue = [&](int kt, int s) {
        cp_async16(sb + OFF_A + s * ST_A + dstA_off,
                   g_A + ((size_t)(kt * 4 + ckl) * MTOT + m0 + cm) * 4);
        const float4* bsrc = (const float4*)(g_wB + (size_t)kt * 4096);
#pragma unroll
        for (int r = 0; r < 2; r++)
            cp_async16(sb + OFF_B + s * ST_B + (r * 512 + tid) * 16,
                       bsrc + r * 512 + tid);
        asm volatile("cp.async.commit_group;" ::: "memory");
    };

    float acc[2][8][4];
#pragma unroll
    for (int mt = 0; mt < 2; mt++)
#pragma unroll
        for (int nt = 0; nt < 8; nt++)
#pragma unroll
            for (int r = 0; r < 4; r++) acc[mt][nt][r] = 0.f;

    auto compute = [&](int s) {
        const uint32_t Ab = sb + OFF_A + s * ST_A;
        const uint32_t Bb = sb + OFF_B + s * ST_B;
#pragma unroll
        for (int k16 = 0; k16 < 2; k16++) {
            uint32_t a[2][4];
#pragma unroll
            for (int mt = 0; mt < 2; mt++) {
                int mr = wm * 32 + mt * 16;
                int t = lane >> 3, r = lane & 7;
                int mrow = mr + ((t & 1) << 3) + r;
                int rp = mrow >> 1;
                int cc = ((mrow & 1) << 2) + (k16 << 1) + (t >> 1);
                uint32_t addr = Ab + rp * 128 + ((cc ^ (rp & 7)) << 4);
                asm volatile(
                    "ldmatrix.sync.aligned.m8n8.x4.shared.b16 {%0,%1,%2,%3}, [%4];"
                    : "=r"(a[mt][0]), "=r"(a[mt][1]), "=r"(a[mt][2]), "=r"(a[mt][3])
                    : "r"(addr));
            }
#pragma unroll
            for (int j = 0; j < 4; j++) {
                uint32_t b0, b1, b2, b3;
                uint32_t addr = Bb + (((k16 * 16) + wn * 4 + j) * 32 + lane) * 16;
                asm volatile("ld.shared.v4.u32 {%0,%1,%2,%3}, [%4];"
                             : "=r"(b0), "=r"(b1), "=r"(b2), "=r"(b3) : "r"(addr));
                mma_f16(acc[0][2 * j],     a[0], b0, b1);
                mma_f16(acc[1][2 * j],     a[1], b0, b1);
                mma_f16(acc[0][2 * j + 1], a[0], b2, b3);
                mma_f16(acc[1][2 * j + 1], a[1], b2, b3);
            }
        }
    };

    issue(0, 0);
    issue(1, 1);
    asm volatile("cp.async.wait_group 1;" ::: "memory");
    __syncthreads();

    for (int kt = 0; kt < NCHUNK; kt++) {
        compute(kt % 3);
        __syncthreads();
        if (kt + 2 < NCHUNK) {
            issue(kt + 2, (kt + 2) % 3);
            asm volatile("cp.async.wait_group 1;" ::: "memory");
        } else {
            asm volatile("cp.async.wait_group 0;" ::: "memory");
        }
        __syncthreads();
    }

    // epilogue: acc -> g_raw[b][n][hw]
    const int hwb = (m0 & 4095);
#pragma unroll
    for (int mt = 0; mt < 2; mt++) {
        int hw0 = hwb + wm * 32 + mt * 16 + g;
#pragma unroll
        for (int nt = 0; nt < 8; nt++) {
            int n = wn * 64 + nt * 8 + 2 * tg;
            float* p0 = g_raw + ((size_t)(b * CO + n) << 12);
            float* p1 = p0 + HW;
            p0[hw0]     = acc[mt][nt][0];
            p1[hw0]     = acc[mt][nt][1];
            p0[hw0 + 8] = acc[mt][nt][2];
            p1[hw0 + 8] = acc[mt][nt][3];
        }
    }
}

// ---------------- BN ----------------
__global__ void bn_stats(const float* __restrict__ gamma,
                         const float* __restrict__ beta) {
    int o = blockIdx.x;
    int tid = threadIdx.x;
    float s = 0.f, s2 = 0.f;
#pragma unroll
    for (int b = 0; b < BB; b++) {
        const float* p = g_raw + (size_t)((b * CO + o) << 12);
        for (int i = tid; i < HW; i += 256) {
            float v = p[i];
            s += v;
            s2 += v * v;
        }
    }
    __shared__ float sh[256], sh2[256];
    sh[tid] = s; sh2[tid] = s2;
    __syncthreads();
    for (int st = 128; st > 0; st >>= 1) {
        if (tid < st) { sh[tid] += sh[tid + st]; sh2[tid] += sh2[tid + st]; }
        __syncthreads();
    }
    if (tid == 0) {
        float mean = sh[0] * (1.f / 16384.f);
        float var  = sh2[0] * (1.f / 16384.f) - mean * mean;
        float inv  = gamma[o] * rsqrtf(var + 1e-5f);
        g_scale[o] = inv;
        g_shift[o] = beta[o] - mean * inv;
    }
}

__global__ void bn_apply(float* __restrict__ out) {
    int t = blockIdx.x * 256 + threadIdx.x;
    int o = (t >> 10) & 255;
    float4 v = ((const float4*)g_raw)[t];
    float sc = g_scale[o], sf = g_shift[o];
    float4 r;
    r.x = fmaxf(v.x * sc + sf, 0.f);
    r.y = fmaxf(v.y * sc + sf, 0.f);
    r.z = fmaxf(v.z * sc + sf, 0.f);
    r.w = fmaxf(v.w * sc + sf, 0.f);
    ((float4*)out)[t] = r;
}

// ---------------- launch ----------------
extern "C" void kernel_launch(void* const* d_in, const int* in_sizes, int n_in,
                              void* d_out, int out_size) {
    const float* x      = (const float*)d_in[0];
    const float* w_off  = (const float*)d_in[1];
    const float* b_off  = (const float*)d_in[2];
    const float* w_conv = (const float*)d_in[3];
    const float* gamma  = (const float*)d_in[4];
    const float* beta   = (const float*)d_in[5];
    float* out = (float*)d_out;

    cudaFuncSetAttribute(gemm_main,
                         cudaFuncAttributeMaxDynamicSharedMemorySize, SMEM_GEMM);

    prep_wB<<<(NCHUNK * 4096) / 256, 256>>>(w_conv);
    offset_partial<<<dim3(BB * 16, 4), 256>>>(x, w_off);
    offset_reduce<<<(BB * 18 * HW + 255) / 256, 256>>>(b_off);
    gather_A_kernel<<<dim3(MTOT / 128, 9), 256>>>(x);
    gemm_main<<<MTOT / 128, 512, SMEM_GEMM>>>(0);
    bn_stats<<<CO, 256>>>(gamma, beta);
    bn_apply<<<(BB * CO * HW / 4) / 256, 256>>>(out);
}

// round 7
// speedup vs baseline: 1.0526x; 1.0526x over previous
#include <cuda_runtime.h>
#include <cuda_fp16.h>
#include <cstdint>

#define BB 4
#define CI 256
#define CO 256
#define HH 64
#define WW 64
#define HW 4096
#define KD 2304          // CI * 9
#define MTOT 16384
#define KC 32
#define NCHUNK 72        // KD / KC

// ---------------- scratch ----------------
__device__ float g_poff[4 * BB * 18 * HW];
__device__ float g_off[BB * 18 * HW];
__device__ __align__(16) uint32_t g_wB[NCHUNK * 4096];     // frag-ordered fp16 B
__device__ __align__(16) uint32_t g_A[288 * MTOT * 4];     // sampled A fp16
__device__ __align__(16) __half g_xh[BB * CI * HW];        // fp16 copy of x
__device__ __align__(16) float g_raw[BB * CO * HW];
__device__ float g_sum[CO];
__device__ float g_sum2[CO];
__device__ float g_scale[CO];
__device__ float g_shift[CO];

// ---------------- helpers ----------------
__device__ __forceinline__ uint32_t smem_u32(const void* p) {
    uint32_t a;
    asm("{ .reg .u64 t; cvta.to.shared.u64 t, %1; cvt.u32.u64 %0, t; }" : "=r"(a) : "l"(p));
    return a;
}
__device__ __forceinline__ uint32_t pack_h2(float lo, float hi) {
    __half2 h = __floats2half2_rn(lo, hi);
    return *(uint32_t*)&h;
}
__device__ __forceinline__ void mma_f16(float* d, const uint32_t* a,
                                        uint32_t b0, uint32_t b1) {
    asm volatile(
        "mma.sync.aligned.m16n8k16.row.col.f32.f16.f16.f32 "
        "{%0,%1,%2,%3}, {%4,%5,%6,%7}, {%8,%9}, {%0,%1,%2,%3};"
        : "+f"(d[0]), "+f"(d[1]), "+f"(d[2]), "+f"(d[3])
        : "r"(a[0]), "r"(a[1]), "r"(a[2]), "r"(a[3]), "r"(b0), "r"(b1));
}
__device__ __forceinline__ void cp_async16(uint32_t saddr, const void* gaddr) {
    asm volatile("cp.async.cg.shared.global [%0], [%1], 16;" :: "r"(saddr), "l"(gaddr));
}

// ---------------- kernel: x -> fp16 ----------------------------------------
__global__ void prep_xh(const float* __restrict__ x) {
    int t = blockIdx.x * 256 + threadIdx.x;     // over 1,048,576 float4 groups
    float4 v = ((const float4*)x)[t];
    uint2 o;
    o.x = pack_h2(v.x, v.y);
    o.y = pack_h2(v.z, v.w);
    ((uint2*)g_xh)[t] = o;
}

// ---------------- kernel: zero stats ----------------------------------------
__global__ void zero_stats() {
    int t = threadIdx.x;
    g_sum[t] = 0.f;
    g_sum2[t] = 0.f;
}

// ---------------- kernel: pack B into fragment order (fp16) ---------------
__global__ void prep_wB(const float* __restrict__ w_conv) {
    int idx = blockIdx.x * 256 + threadIdx.x;
    if (idx >= NCHUNK * 4096) return;
    int kt = idx >> 12;
    int r  = idx & 4095;
    int k16  = r >> 11;
    int np   = (r >> 7) & 15;
    int lane = (r >> 2) & 31;
    int w    = r & 3;
    int g = lane >> 2, tg = lane & 3;
    int nt = np * 2 + (w >> 1);
    int h  = w & 1;
    int n  = nt * 8 + g;
    int ck = kt * KC + k16 * 16 + h * 8 + 2 * tg;
    g_wB[idx] = pack_h2(w_conv[n * KD + ck], w_conv[n * KD + ck + 1]);
}

// ---------------- offset conv partials -------------------------------------
__global__ void offset_partial(const float* __restrict__ x,
                               const float* __restrict__ w_off) {
    __shared__ __align__(16) float ws[8 * 164];
    int b  = blockIdx.x >> 4;
    int hq = blockIdx.x & 15;
    int cq = blockIdx.y;
    int tid = threadIdx.x;
    int h = hq * 4 + (tid >> 6);
    int w = tid & 63;

    unsigned long long acc2[9];
#pragma unroll
    for (int p = 0; p < 9; p++) acc2[p] = 0ULL;

    const float* xb = x + (size_t)b * CI * HW;

    for (int cc = 0; cc < 64; cc += 8) {
        int c0 = cq * 64 + cc;
        for (int e = tid; e < 8 * 162; e += 256) {
            int ci = e / 162;
            int r  = e - ci * 162;
            int j  = r / 18;
            int o  = r - j * 18;
            ws[ci * 164 + j * 18 + o] = w_off[o * KD + (c0 + ci) * 9 + j];
        }
        __syncthreads();

        for (int ci = 0; ci < 8; ci++) {
            const float* xc = xb + (c0 + ci) * HW;
            float v[9];
#pragma unroll
            for (int ki = 0; ki < 3; ki++) {
                int yy = h + ki - 1;
                bool vy = (yy >= 0 && yy < HH);
#pragma unroll
                for (int kj = 0; kj < 3; kj++) {
                    int xx = w + kj - 1;
                    v[ki * 3 + kj] = (vy && xx >= 0 && xx < WW) ? xc[yy * WW + xx] : 0.f;
                }
            }
#pragma unroll
            for (int j = 0; j < 9; j++) {
                unsigned long long a2;
                asm("mov.b64 %0, {%1, %1};" : "=l"(a2) : "r"(__float_as_uint(v[j])));
                const unsigned long long* ww2 =
                    (const unsigned long long*)(ws + ci * 164 + j * 18);
#pragma unroll
                for (int p = 0; p < 9; p++)
                    asm("fma.rn.f32x2 %0, %1, %2, %0;"
                        : "+l"(acc2[p]) : "l"(a2), "l"(ww2[p]));
            }
        }
        __syncthreads();
    }
#pragma unroll
    for (int p = 0; p < 9; p++) {
        unsigned int ul, uh;
        asm("mov.b64 {%0, %1}, %2;" : "=r"(ul), "=r"(uh) : "l"(acc2[p]));
        g_poff[((cq * 4 + b) * 18 + 2 * p)     * HW + h * WW + w] = __uint_as_float(ul);
        g_poff[((cq * 4 + b) * 18 + 2 * p + 1) * HW + h * WW + w] = __uint_as_float(uh);
    }
}

__global__ void offset_reduce(const float* __restrict__ b_off) {
    int idx = blockIdx.x * 256 + threadIdx.x;
    if (idx >= BB * 18 * HW) return;
    int hw = idx & 4095;
    int bo = idx >> 12;
    int b = bo / 18;
    int o = bo - b * 18;
    float s = b_off[o];
#pragma unroll
    for (int cq = 0; cq < 4; cq++)
        s += g_poff[((cq * 4 + b) * 18 + o) * HW + hw];
    g_off[idx] = s;
}

// ---------------- kernel: deformable gather (fp16 x) -> fp16 A -------------
__global__ void __launch_bounds__(256) gather_A_kernel() {
    __shared__ __align__(16) ushort4 gidx[9 * 128];
    __shared__ __align__(16) float4  gwts[9 * 128];
    const int tid = threadIdx.x;
    const int m0 = blockIdx.x << 7;
    const int b  = m0 >> 12;
    const __half* xb = g_xh + ((size_t)b * CI << 12);

    for (int e = tid; e < 9 * 128; e += 256) {
        int k  = e >> 7;
        int mm = e & 127;
        int hw = (m0 + mm) & 4095;
        int h  = hw >> 6;
        int w  = hw & 63;
        float offy = g_off[(b * 18 + 2 * k) * HW + hw];
        float offx = g_off[(b * 18 + 2 * k + 1) * HW + hw];
        int k3 = k / 3;
        float py = (float)(h + k3 - 1) + offy;
        float px = (float)(w + (k - k3 * 3) - 1) + offx;
        float fy0 = floorf(py), fx0 = floorf(px);
        float wy1 = py - fy0, wx1 = px - fx0;
        float wy0 = 1.f - wy1, wx0 = 1.f - wx1;
        int iy0 = (int)fy0, ix0 = (int)fx0;
        int iy1 = iy0 + 1, ix1 = ix0 + 1;
        float vy0 = (iy0 >= 0 && iy0 < HH) ? 1.f : 0.f;
        float vy1 = (iy1 >= 0 && iy1 < HH) ? 1.f : 0.f;
        float vx0 = (ix0 >= 0 && ix0 < WW) ? 1.f : 0.f;
        float vx1 = (ix1 >= 0 && ix1 < WW) ? 1.f : 0.f;
        int cy0 = min(max(iy0, 0), HH - 1), cy1 = min(max(iy1, 0), HH - 1);
        int cx0 = min(max(ix0, 0), WW - 1), cx1 = min(max(ix1, 0), WW - 1);
        ushort4 gi;
        gi.x = (unsigned short)(cy0 * WW + cx0);
        gi.y = (unsigned short)(cy0 * WW + cx1);
        gi.z = (unsigned short)(cy1 * WW + cx0);
        gi.w = (unsigned short)(cy1 * WW + cx1);
        gidx[e] = gi;
        gwts[e] = make_float4(wy0 * wx0 * vy0 * vx0,
                              wy0 * wx1 * vy0 * vx1,
                              wy1 * wx0 * vy1 * vx0,
                              wy1 * wx1 * vy1 * vx1);
    }
    __syncthreads();

    const int mm = tid & 127;
    const int ch = tid >> 7;
    const int kb0 = blockIdx.y * 256;

#pragma unroll 1
    for (int it = 0; it < 16; it++) {
        int kc_in = ch + it * 2;
        int ckb = kb0 + kc_in * 8;
        float v[8];
#pragma unroll
        for (int s = 0; s < 8; s++) {
            int ck = ckb + s;
            int c = ck / 9;
            int tap = ck - c * 9;
            ushort4 gi = gidx[tap * 128 + mm];
            float4  gw = gwts[tap * 128 + mm];
            const __half* xc = xb + ((size_t)c << 12);
            v[s] = gw.x * __half2float(__ldg(xc + gi.x))
                 + gw.y * __half2float(__ldg(xc + gi.y))
                 + gw.z * __half2float(__ldg(xc + gi.z))
                 + gw.w * __half2float(__ldg(xc + gi.w));
        }
        uint4 wv;
        wv.x = pack_h2(v[0], v[1]);
        wv.y = pack_h2(v[2], v[3]);
        wv.z = pack_h2(v[4], v[5]);
        wv.w = pack_h2(v[6], v[7]);
        int kc = (kb0 >> 3) + kc_in;
        *(uint4*)(g_A + ((size_t)kc * MTOT + m0 + mm) * 4) = wv;
    }
}

// ---------------- kernel: pipelined fp16 HMMA GEMM -------------------------
// 128(m) x 128(n) tile, 256 thr, 8 warps (4x2), KC=32, 3-stage, 2 blocks/SM.
#define ST_A 8192
#define ST_B 8192
#define OFF_A 0
#define OFF_B (3 * ST_A)
#define SMEM_GEMM (3 * ST_A + 3 * ST_B)     // 49152

__global__ void __launch_bounds__(256, 2)
gemm_main() {
    extern __shared__ char smem[];
    const uint32_t sb = smem_u32(smem);
    const int tid  = threadIdx.x;
    const int lane = tid & 31;
    const int wid  = tid >> 5;
    const int g  = lane >> 2;
    const int tg = lane & 3;
    const int wm = wid & 3;
    const int wn = wid >> 2;                 // 0..1
    const int m0 = blockIdx.x << 7;
    const int by = blockIdx.y;               // n half
    const int b  = m0 >> 12;

    // cp.async mapping for A: thread covers (cm, ckl) and (cm, ckl+2)
    const int cm   = tid & 127;
    const int ckl0 = tid >> 7;               // 0..1

    auto issue = [&](int kt, int s) {
#pragma unroll
        for (int q = 0; q < 2; q++) {
            int ckl = ckl0 + q * 2;
            uint32_t dstA = (uint32_t)((cm >> 1) * 128
                         + (((((cm & 1) << 2) + ckl) ^ ((cm >> 1) & 7)) << 4));
            cp_async16(sb + OFF_A + s * ST_A + dstA,
                       g_A + ((size_t)(kt * 4 + ckl) * MTOT + m0 + cm) * 4);
        }
        const float4* wb4 = (const float4*)g_wB;
#pragma unroll
        for (int r = 0; r < 2; r++) {
            int idx = r * 256 + tid;
            int k16 = idx >> 8;
            int npl = (idx >> 5) & 7;
            int ln  = idx & 31;
            cp_async16(sb + OFF_B + s * ST_B + idx * 16,
                       wb4 + (size_t)kt * 1024 + k16 * 512 + (8 * by + npl) * 32 + ln);
        }
        asm volatile("cp.async.commit_group;" ::: "memory");
    };

    float acc[2][8][4];
#pragma unroll
    for (int mt = 0; mt < 2; mt++)
#pragma unroll
        for (int nt = 0; nt < 8; nt++)
#pragma unroll
            for (int r = 0; r < 4; r++) acc[mt][nt][r] = 0.f;

    auto compute = [&](int s) {
        const uint32_t Ab = sb + OFF_A + s * ST_A;
        const uint32_t Bb = sb + OFF_B + s * ST_B;
#pragma unroll
        for (int k16 = 0; k16 < 2; k16++) {
            uint32_t a[2][4];
#pragma unroll
            for (int mt = 0; mt < 2; mt++) {
                int mr = wm * 32 + mt * 16;
                int t = lane >> 3, r = lane & 7;
                int mrow = mr + ((t & 1) << 3) + r;
                int rp = mrow >> 1;
                int cc = ((mrow & 1) << 2) + (k16 << 1) + (t >> 1);
                uint32_t addr = Ab + rp * 128 + ((cc ^ (rp & 7)) << 4);
                asm volatile(
                    "ldmatrix.sync.aligned.m8n8.x4.shared.b16 {%0,%1,%2,%3}, [%4];"
                    : "=r"(a[mt][0]), "=r"(a[mt][1]), "=r"(a[mt][2]), "=r"(a[mt][3])
                    : "r"(addr));
            }
#pragma unroll
            for (int j = 0; j < 4; j++) {
                uint32_t b0, b1, b2, b3;
                uint32_t addr = Bb + (((k16 * 8) + wn * 4 + j) * 32 + lane) * 16;
                asm volatile("ld.shared.v4.u32 {%0,%1,%2,%3}, [%4];"
                             : "=r"(b0), "=r"(b1), "=r"(b2), "=r"(b3) : "r"(addr));
                mma_f16(acc[0][2 * j],     a[0], b0, b1);
                mma_f16(acc[1][2 * j],     a[1], b0, b1);
                mma_f16(acc[0][2 * j + 1], a[0], b2, b3);
                mma_f16(acc[1][2 * j + 1], a[1], b2, b3);
            }
        }
    };

    issue(0, 0);
    issue(1, 1);
    asm volatile("cp.async.wait_group 1;" ::: "memory");
    __syncthreads();

    for (int kt = 0; kt < NCHUNK; kt++) {
        compute(kt % 3);
        __syncthreads();
        if (kt + 2 < NCHUNK) {
            issue(kt + 2, (kt + 2) % 3);
            asm volatile("cp.async.wait_group 1;" ::: "memory");
        } else {
            asm volatile("cp.async.wait_group 0;" ::: "memory");
        }
        __syncthreads();
    }

    // epilogue: store + per-channel stats
    const int hwb = (m0 & 4095);
#pragma unroll
    for (int nt = 0; nt < 8; nt++) {
        int n = by * 128 + wn * 64 + nt * 8 + 2 * tg;
        float* p0 = g_raw + ((size_t)(b * CO + n) << 12);
        float* p1 = p0 + HW;
        float s0 = 0.f, q0 = 0.f, s1 = 0.f, q1 = 0.f;
#pragma unroll
        for (int mt = 0; mt < 2; mt++) {
            int hw0 = hwb + wm * 32 + mt * 16 + g;
            float d0 = acc[mt][nt][0], d1 = acc[mt][nt][1];
            float d2 = acc[mt][nt][2], d3 = acc[mt][nt][3];
            p0[hw0]     = d0;
            p1[hw0]     = d1;
            p0[hw0 + 8] = d2;
            p1[hw0 + 8] = d3;
            s0 += d0 + d2;  q0 += d0 * d0 + d2 * d2;
            s1 += d1 + d3;  q1 += d1 * d1 + d3 * d3;
        }
#pragma unroll
        for (int o = 4; o < 32; o <<= 1) {
            s0 += __shfl_xor_sync(0xFFFFFFFF, s0, o);
            q0 += __shfl_xor_sync(0xFFFFFFFF, q0, o);
            s1 += __shfl_xor_sync(0xFFFFFFFF, s1, o);
            q1 += __shfl_xor_sync(0xFFFFFFFF, q1, o);
        }
        if (lane < 4) {
            atomicAdd(&g_sum[n], s0);
            atomicAdd(&g_sum2[n], q0);
            atomicAdd(&g_sum[n + 1], s1);
            atomicAdd(&g_sum2[n + 1], q1);
        }
    }
}

// ---------------- BN finalize + apply ---------------------------------------
__global__ void bn_finalize(const float* __restrict__ gamma,
                            const float* __restrict__ beta) {
    int o = threadIdx.x;
    float mean = g_sum[o] * (1.f / 16384.f);
    float var  = g_sum2[o] * (1.f / 16384.f) - mean * mean;
    float inv  = gamma[o] * rsqrtf(var + 1e-5f);
    g_scale[o] = inv;
    g_shift[o] = beta[o] - mean * inv;
}

__global__ void bn_apply(float* __restrict__ out) {
    int t = blockIdx.x * 256 + threadIdx.x;
    int o = (t >> 10) & 255;
    float4 v = ((const float4*)g_raw)[t];
    float sc = g_scale[o], sf = g_shift[o];
    float4 r;
    r.x = fmaxf(v.x * sc + sf, 0.f);
    r.y = fmaxf(v.y * sc + sf, 0.f);
    r.z = fmaxf(v.z * sc + sf, 0.f);
    r.w = fmaxf(v.w * sc + sf, 0.f);
    ((float4*)out)[t] = r;
}

// ---------------- launch ----------------
extern "C" void kernel_launch(void* const* d_in, const int* in_sizes, int n_in,
                              void* d_out, int out_size) {
    const float* x      = (const float*)d_in[0];
    const float* w_off  = (const float*)d_in[1];
    const float* b_off  = (const float*)d_in[2];
    const float* w_conv = (const float*)d_in[3];
    const float* gamma  = (const float*)d_in[4];
    const float* beta   = (const float*)d_in[5];
    float* out = (float*)d_out;

    cudaFuncSetAttribute(gemm_main,
                         cudaFuncAttributeMaxDynamicSharedMemorySize, SMEM_GEMM);

    prep_xh<<<(BB * CI * HW / 4) / 256, 256>>>(x);
    prep_wB<<<(NCHUNK * 4096) / 256, 256>>>(w_conv);
    zero_stats<<<1, 256>>>();
    offset_partial<<<dim3(BB * 16, 4), 256>>>(x, w_off);
    offset_reduce<<<(BB * 18 * HW + 255) / 256, 256>>>(b_off);
    gather_A_kernel<<<dim3(MTOT / 128, 9), 256>>>();
    gemm_main<<<dim3(MTOT / 128, 2), 256, SMEM_GEMM>>>();
    bn_finalize<<<1, 256>>>(gamma, beta);
    bn_apply<<<(BB * CO * HW / 4) / 256, 256>>>(out);
}

// round 8
// speedup vs baseline: 1.1737x; 1.1151x over previous
#include <cuda_runtime.h>
#include <cuda_fp16.h>
#include <cstdint>

#define BB 4
#define CI 256
#define CO 256
#define HH 64
#define WW 64
#define HW 4096
#define KD 2304          // CI * 9
#define MTOT 16384
#define KC 32
#define NCHUNK 72        // KD / KC
#define PP 4356          // 66*66 padded pixels

// ---------------- scratch ----------------
__device__ float g_off[BB * 18 * HW];
__device__ __align__(16) uint32_t g_wB[NCHUNK * 4096];     // frag-ordered fp16 B (main)
__device__ __align__(16) uint32_t g_wOffB[NCHUNK * 384];   // frag-ordered fp16 B (offset, N=24)
__device__ __align__(16) uint32_t g_A[288 * MTOT * 4];     // sampled A fp16
__device__ __align__(16) __half g_xh[BB * CI * HW];        // fp16 x, (c, hw)
__device__ __align__(16) __half g_xTp[BB * PP * CI];       // fp16 x, padded transposed (hw, c)
__device__ __align__(16) ushort4 g_tidx[9 * MTOT];         // bilinear corner indices
__device__ __align__(16) float4  g_twts[9 * MTOT];         // bilinear corner weights
__device__ __align__(16) float g_raw[BB * CO * HW];
__device__ float g_sum[CO];
__device__ float g_sum2[CO];
__device__ float g_scale[CO];
__device__ float g_shift[CO];

// ---------------- helpers ----------------
__device__ __forceinline__ uint32_t smem_u32(const void* p) {
    uint32_t a;
    asm("{ .reg .u64 t; cvta.to.shared.u64 t, %1; cvt.u32.u64 %0, t; }" : "=r"(a) : "l"(p));
    return a;
}
__device__ __forceinline__ uint32_t pack_h2(float lo, float hi) {
    __half2 h = __floats2half2_rn(lo, hi);
    return *(uint32_t*)&h;
}
__device__ __forceinline__ void mma_f16(float* d, const uint32_t* a,
                                        uint32_t b0, uint32_t b1) {
    asm volatile(
        "mma.sync.aligned.m16n8k16.row.col.f32.f16.f16.f32 "
        "{%0,%1,%2,%3}, {%4,%5,%6,%7}, {%8,%9}, {%0,%1,%2,%3};"
        : "+f"(d[0]), "+f"(d[1]), "+f"(d[2]), "+f"(d[3])
        : "r"(a[0]), "r"(a[1]), "r"(a[2]), "r"(a[3]), "r"(b0), "r"(b1));
}
__device__ __forceinline__ void cp_async16(uint32_t saddr, const void* gaddr) {
    asm volatile("cp.async.cg.shared.global [%0], [%1], 16;" :: "r"(saddr), "l"(gaddr));
}

// ---------------- kernel: zero xTp borders ---------------------------------
__global__ void zero_pad_xT() {
    int idx = blockIdx.x * 256 + threadIdx.x;   // 4*260*32
    if (idx >= BB * 260 * 32) return;
    int q = idx & 31;
    int r = (idx >> 5) % 260;
    int b = idx / (260 * 32);
    int row;
    if (r < 66)       row = r;
    else if (r < 132) row = 65 * 66 + (r - 66);
    else if (r < 196) row = (r - 132 + 1) * 66;
    else              row = (r - 196 + 1) * 66 + 65;
    ((uint4*)(g_xTp + ((size_t)b * PP + row) * CI))[q] = make_uint4(0, 0, 0, 0);
}

// ---------------- kernel: x -> fp16 (c-major) + padded transpose -----------
__global__ void prep_xhT(const float* __restrict__ x) {
    __shared__ float tile[64][65];
    int bh = blockIdx.x;            // b*64 + h
    int c0 = blockIdx.y * 64;
    int b = bh >> 6, h = bh & 63;
    int t = threadIdx.x;
    int ci = t >> 6, w = t & 63;
#pragma unroll
    for (int rep = 0; rep < 16; rep++) {
        int c = c0 + ci + rep * 4;
        size_t gi = ((size_t)(b * CI + c) << 12) + h * 64 + w;
        float v = x[gi];
        g_xh[gi] = __float2half(v);
        tile[ci + rep * 4][w] = v;
    }
    __syncthreads();
#pragma unroll
    for (int rep = 0; rep < 2; rep++) {
        int e = t + rep * 256;
        int w2 = e & 63, q = e >> 6;
        __half hv[8];
#pragma unroll
        for (int j = 0; j < 8; j++) hv[j] = __float2half(tile[q * 8 + j][w2]);
        size_t dst = ((size_t)b * PP + (h + 1) * 66 + (w2 + 1)) * CI + c0 + q * 8;
        *(uint4*)(g_xTp + dst) = *(uint4*)hv;
    }
}

// ---------------- kernel: zero stats ----------------------------------------
__global__ void zero_stats() {
    int t = threadIdx.x;
    g_sum[t] = 0.f;
    g_sum2[t] = 0.f;
}

// ---------------- kernel: pack main B into fragment order ------------------
__global__ void prep_wB(const float* __restrict__ w_conv) {
    int idx = blockIdx.x * 256 + threadIdx.x;
    if (idx >= NCHUNK * 4096) return;
    int kt = idx >> 12;
    int r  = idx & 4095;
    int k16  = r >> 11;
    int np   = (r >> 7) & 15;
    int lane = (r >> 2) & 31;
    int w    = r & 3;
    int g = lane >> 2, tg = lane & 3;
    int nt = np * 2 + (w >> 1);
    int h  = w & 1;
    int n  = nt * 8 + g;
    int ck = kt * KC + k16 * 16 + h * 8 + 2 * tg;
    g_wB[idx] = pack_h2(w_conv[n * KD + ck], w_conv[n * KD + ck + 1]);
}

// ---------------- kernel: pack offset B (N=24, K tap-major) ----------------
// layout: [kt][k16(2)][nt(3)][lane(32)*2 + h]
__global__ void prep_wOffB(const float* __restrict__ w_off) {
    int idx = blockIdx.x * 256 + threadIdx.x;
    if (idx >= NCHUNK * 384) return;
    int kt = idx / 384;
    int r  = idx - kt * 384;
    int k16  = r / 192;
    int nt   = (r / 64) % 3;
    int lane = (r >> 1) & 31;
    int h    = r & 1;
    int g = lane >> 2, tg = lane & 3;
    int n = nt * 8 + g;
    int tap = kt >> 3;
    int c = (kt & 7) * 32 + k16 * 16 + h * 8 + 2 * tg;
    uint32_t val = 0;
    if (n < 18)
        val = pack_h2(w_off[n * KD + c * 9 + tap], w_off[n * KD + (c + 1) * 9 + tap]);
    g_wOffB[idx] = val;
}

// ---------------- kernel: offset conv as HMMA GEMM -------------------------
// M-tile 128, N=24, K=2304 (tap-major), 128 threads, 3-stage.
__global__ void __launch_bounds__(128)
offset_gemm(const float* __restrict__ b_off) {
    __shared__ __align__(16) char As[3 * 8192];
    __shared__ __align__(16) char Bs[3 * 1536];
    const uint32_t Ab0 = smem_u32(As);
    const uint32_t Bb0 = smem_u32(Bs);
    const int t = threadIdx.x;
    const int lane = t & 31;
    const int wm = t >> 5;
    const int g = lane >> 2;
    const int tg = lane & 3;
    const int m0 = blockIdx.x << 7;
    const int b  = m0 >> 12;

    // this thread's A row
    const int hw = (m0 + t) & 4095;
    const int prow = ((hw >> 6) + 1) * 66 + (hw & 63) + 1;
    const __half* arow = g_xTp + ((size_t)b * PP + prow) * CI;
    const int rp = t >> 1;
    const uint32_t dstA_base = rp * 128;

    auto issue = [&](int kt, int s) {
        int tap = kt >> 3;
        int shift = (tap / 3 - 1) * 66 + (tap % 3 - 1);
        const __half* src = arow + (size_t)shift * CI + (kt & 7) * 32;
#pragma unroll
        for (int q = 0; q < 4; q++) {
            uint32_t cc = ((t & 1) << 2) + q;
            cp_async16(Ab0 + s * 8192 + dstA_base + ((cc ^ (rp & 7)) << 4), src + q * 8);
        }
        if (t < 96)
            cp_async16(Bb0 + s * 1536 + t * 16, g_wOffB + kt * 384 + t * 4);
        asm volatile("cp.async.commit_group;" ::: "memory");
    };

    float acc[2][3][4];
#pragma unroll
    for (int mt = 0; mt < 2; mt++)
#pragma unroll
        for (int nt = 0; nt < 3; nt++)
#pragma unroll
            for (int r = 0; r < 4; r++) acc[mt][nt][r] = 0.f;

    auto compute = [&](int s) {
        const uint32_t Ab = Ab0 + s * 8192;
        const uint32_t Bb = Bb0 + s * 1536;
#pragma unroll
        for (int k16 = 0; k16 < 2; k16++) {
            uint32_t a[2][4];
#pragma unroll
            for (int mt = 0; mt < 2; mt++) {
                int mr = wm * 32 + mt * 16;
                int tt = lane >> 3, r = lane & 7;
                int mrow = mr + ((tt & 1) << 3) + r;
                int rp2 = mrow >> 1;
                int cc = ((mrow & 1) << 2) + (k16 << 1) + (tt >> 1);
                uint32_t addr = Ab + rp2 * 128 + ((cc ^ (rp2 & 7)) << 4);
                asm volatile(
                    "ldmatrix.sync.aligned.m8n8.x4.shared.b16 {%0,%1,%2,%3}, [%4];"
                    : "=r"(a[mt][0]), "=r"(a[mt][1]), "=r"(a[mt][2]), "=r"(a[mt][3])
                    : "r"(addr));
            }
#pragma unroll
            for (int nt = 0; nt < 3; nt++) {
                uint32_t b0, b1;
                uint32_t addr = Bb + ((k16 * 3 + nt) * 64 + lane * 2) * 4;
                asm volatile("ld.shared.v2.u32 {%0,%1}, [%2];"
                             : "=r"(b0), "=r"(b1) : "r"(addr));
                mma_f16(acc[0][nt], a[0], b0, b1);
                mma_f16(acc[1][nt], a[1], b0, b1);
            }
        }
    };

    issue(0, 0);
    issue(1, 1);
    asm volatile("cp.async.wait_group 1;" ::: "memory");
    __syncthreads();

    for (int kt = 0; kt < NCHUNK; kt++) {
        compute(kt % 3);
        __syncthreads();
        if (kt + 2 < NCHUNK) {
            issue(kt + 2, (kt + 2) % 3);
            asm volatile("cp.async.wait_group 1;" ::: "memory");
        } else {
            asm volatile("cp.async.wait_group 0;" ::: "memory");
        }
        __syncthreads();
    }

    // epilogue: write g_off[(b*18+o)*HW + hw] = acc + bias
#pragma unroll
    for (int nt = 0; nt < 3; nt++) {
        int o0 = nt * 8 + 2 * tg;
#pragma unroll
        for (int mt = 0; mt < 2; mt++) {
            int hwm = (m0 & 4095) + wm * 32 + mt * 16 + g;
            if (o0 < 18) {
                float bia = b_off[o0];
                g_off[(b * 18 + o0) * HW + hwm]     = acc[mt][nt][0] + bia;
                g_off[(b * 18 + o0) * HW + hwm + 8] = acc[mt][nt][2] + bia;
            }
            if (o0 + 1 < 18) {
                float bia = b_off[o0 + 1];
                g_off[(b * 18 + o0 + 1) * HW + hwm]     = acc[mt][nt][1] + bia;
                g_off[(b * 18 + o0 + 1) * HW + hwm + 8] = acc[mt][nt][3] + bia;
            }
        }
    }
}

// ---------------- kernel: bilinear tables -----------------------------------
__global__ void tab_kernel() {
    int idx = blockIdx.x * 256 + threadIdx.x;   // 9 * 16384
    int k = idx >> 14;
    int m = idx & 16383;
    int b = m >> 12;
    int hw = m & 4095;
    int h = hw >> 6;
    int w = hw & 63;
    float offy = g_off[(b * 18 + 2 * k) * HW + hw];
    float offx = g_off[(b * 18 + 2 * k + 1) * HW + hw];
    int k3 = k / 3;
    float py = (float)(h + k3 - 1) + offy;
    float px = (float)(w + (k - k3 * 3) - 1) + offx;
    float fy0 = floorf(py), fx0 = floorf(px);
    float wy1 = py - fy0, wx1 = px - fx0;
    float wy0 = 1.f - wy1, wx0 = 1.f - wx1;
    int iy0 = (int)fy0, ix0 = (int)fx0;
    int iy1 = iy0 + 1, ix1 = ix0 + 1;
    float vy0 = (iy0 >= 0 && iy0 < HH) ? 1.f : 0.f;
    float vy1 = (iy1 >= 0 && iy1 < HH) ? 1.f : 0.f;
    float vx0 = (ix0 >= 0 && ix0 < WW) ? 1.f : 0.f;
    float vx1 = (ix1 >= 0 && ix1 < WW) ? 1.f : 0.f;
    int cy0 = min(max(iy0, 0), HH - 1), cy1 = min(max(iy1, 0), HH - 1);
    int cx0 = min(max(ix0, 0), WW - 1), cx1 = min(max(ix1, 0), WW - 1);
    ushort4 gi;
    gi.x = (unsigned short)(cy0 * WW + cx0);
    gi.y = (unsigned short)(cy0 * WW + cx1);
    gi.z = (unsigned short)(cy1 * WW + cx0);
    gi.w = (unsigned short)(cy1 * WW + cx1);
    g_tidx[idx] = gi;
    g_twts[idx] = make_float4(wy0 * wx0 * vy0 * vx0,
                              wy0 * wx1 * vy0 * vx1,
                              wy1 * wx0 * vy1 * vx0,
                              wy1 * wx1 * vy1 * vx1);
}

// ---------------- kernel: deformable gather (fp16 x) -> fp16 A -------------
__global__ void __launch_bounds__(256) gather_A_kernel() {
    __shared__ __align__(16) ushort4 gidx[9 * 128];
    __shared__ __align__(16) float4  gwts[9 * 128];
    const int tid = threadIdx.x;
    const int m0 = blockIdx.x << 7;
    const int b  = m0 >> 12;
    const __half* xb = g_xh + ((size_t)b * CI << 12);

    for (int e = tid; e < 9 * 128; e += 256) {
        int k  = e >> 7;
        int mm = e & 127;
        gidx[e] = g_tidx[(k << 14) + m0 + mm];
        gwts[e] = g_twts[(k << 14) + m0 + mm];
    }
    __syncthreads();

    const int mm = tid & 127;
    const int ch = tid >> 7;
    const int kb0 = blockIdx.y * 256;

#pragma unroll 1
    for (int it = 0; it < 16; it++) {
        int kc_in = ch + it * 2;
        int ckb = kb0 + kc_in * 8;
        float v[8];
#pragma unroll
        for (int s = 0; s < 8; s++) {
            int ck = ckb + s;
            int c = ck / 9;
            int tap = ck - c * 9;
            ushort4 gi = gidx[tap * 128 + mm];
            float4  gw = gwts[tap * 128 + mm];
            const __half* xc = xb + ((size_t)c << 12);
            v[s] = gw.x * __half2float(__ldg(xc + gi.x))
                 + gw.y * __half2float(__ldg(xc + gi.y))
                 + gw.z * __half2float(__ldg(xc + gi.z))
                 + gw.w * __half2float(__ldg(xc + gi.w));
        }
        uint4 wv;
        wv.x = pack_h2(v[0], v[1]);
        wv.y = pack_h2(v[2], v[3]);
        wv.z = pack_h2(v[4], v[5]);
        wv.w = pack_h2(v[6], v[7]);
        int kc = (kb0 >> 3) + kc_in;
        *(uint4*)(g_A + ((size_t)kc * MTOT + m0 + mm) * 4) = wv;
    }
}

// ---------------- kernel: pipelined fp16 HMMA GEMM -------------------------
#define ST_A 8192
#define ST_B 8192
#define OFF_A 0
#define OFF_B (3 * ST_A)
#define SMEM_GEMM (3 * ST_A + 3 * ST_B)     // 49152

__global__ void __launch_bounds__(256, 2)
gemm_main() {
    extern __shared__ char smem[];
    const uint32_t sb = smem_u32(smem);
    const int tid  = threadIdx.x;
    const int lane = tid & 31;
    const int wid  = tid >> 5;
    const int g  = lane >> 2;
    const int tg = lane & 3;
    const int wm = wid & 3;
    const int wn = wid >> 2;
    const int m0 = blockIdx.x << 7;
    const int by = blockIdx.y;
    const int b  = m0 >> 12;

    const int cm   = tid & 127;
    const int ckl0 = tid >> 7;

    auto issue = [&](int kt, int s) {
#pragma unroll
        for (int q = 0; q < 2; q++) {
            int ckl = ckl0 + q * 2;
            uint32_t dstA = (uint32_t)((cm >> 1) * 128
                         + (((((cm & 1) << 2) + ckl) ^ ((cm >> 1) & 7)) << 4));
            cp_async16(sb + OFF_A + s * ST_A + dstA,
                       g_A + ((size_t)(kt * 4 + ckl) * MTOT + m0 + cm) * 4);
        }
        const float4* wb4 = (const float4*)g_wB;
#pragma unroll
        for (int r = 0; r < 2; r++) {
            int idx = r * 256 + tid;
            int k16 = idx >> 8;
            int npl = (idx >> 5) & 7;
            int ln  = idx & 31;
            cp_async16(sb + OFF_B + s * ST_B + idx * 16,
                       wb4 + (size_t)kt * 1024 + k16 * 512 + (8 * by + npl) * 32 + ln);
        }
        asm volatile("cp.async.commit_group;" ::: "memory");
    };

    float acc[2][8][4];
#pragma unroll
    for (int mt = 0; mt < 2; mt++)
#pragma unroll
        for (int nt = 0; nt < 8; nt++)
#pragma unroll
            for (int r = 0; r < 4; r++) acc[mt][nt][r] = 0.f;

    auto compute = [&](int s) {
        const uint32_t Ab = sb + OFF_A + s * ST_A;
        const uint32_t Bb = sb + OFF_B + s * ST_B;
#pragma unroll
        for (int k16 = 0; k16 < 2; k16++) {
            uint32_t a[2][4];
#pragma unroll
            for (int mt = 0; mt < 2; mt++) {
                int mr = wm * 32 + mt * 16;
                int t = lane >> 3, r = lane & 7;
                int mrow = mr + ((t & 1) << 3) + r;
                int rp = mrow >> 1;
                int cc = ((mrow & 1) << 2) + (k16 << 1) + (t >> 1);
                uint32_t addr = Ab + rp * 128 + ((cc ^ (rp & 7)) << 4);
                asm volatile(
                    "ldmatrix.sync.aligned.m8n8.x4.shared.b16 {%0,%1,%2,%3}, [%4];"
                    : "=r"(a[mt][0]), "=r"(a[mt][1]), "=r"(a[mt][2]), "=r"(a[mt][3])
                    : "r"(addr));
            }
#pragma unroll
            for (int j = 0; j < 4; j++) {
                uint32_t b0, b1, b2, b3;
                uint32_t addr = Bb + (((k16 * 8) + wn * 4 + j) * 32 + lane) * 16;
                asm volatile("ld.shared.v4.u32 {%0,%1,%2,%3}, [%4];"
                             : "=r"(b0), "=r"(b1), "=r"(b2), "=r"(b3) : "r"(addr));
                mma_f16(acc[0][2 * j],     a[0], b0, b1);
                mma_f16(acc[1][2 * j],     a[1], b0, b1);
                mma_f16(acc[0][2 * j + 1], a[0], b2, b3);
                mma_f16(acc[1][2 * j + 1], a[1], b2, b3);
            }
        }
    };

    issue(0, 0);
    issue(1, 1);
    asm volatile("cp.async.wait_group 1;" ::: "memory");
    __syncthreads();

    for (int kt = 0; kt < NCHUNK; kt++) {
        compute(kt % 3);
        __syncthreads();
        if (kt + 2 < NCHUNK) {
            issue(kt + 2, (kt + 2) % 3);
            asm volatile("cp.async.wait_group 1;" ::: "memory");
        } else {
            asm volatile("cp.async.wait_group 0;" ::: "memory");
        }
        __syncthreads();
    }

    const int hwb = (m0 & 4095);
#pragma unroll
    for (int nt = 0; nt < 8; nt++) {
        int n = by * 128 + wn * 64 + nt * 8 + 2 * tg;
        float* p0 = g_raw + ((size_t)(b * CO + n) << 12);
        float* p1 = p0 + HW;
        float s0 = 0.f, q0 = 0.f, s1 = 0.f, q1 = 0.f;
#pragma unroll
        for (int mt = 0; mt < 2; mt++) {
            int hw0 = hwb + wm * 32 + mt * 16 + g;
            float d0 = acc[mt][nt][0], d1 = acc[mt][nt][1];
            float d2 = acc[mt][nt][2], d3 = acc[mt][nt][3];
            p0[hw0]     = d0;
            p1[hw0]     = d1;
            p0[hw0 + 8] = d2;
            p1[hw0 + 8] = d3;
            s0 += d0 + d2;  q0 += d0 * d0 + d2 * d2;
            s1 += d1 + d3;  q1 += d1 * d1 + d3 * d3;
        }
#pragma unroll
        for (int o = 4; o < 32; o <<= 1) {
            s0 += __shfl_xor_sync(0xFFFFFFFF, s0, o);
            q0 += __shfl_xor_sync(0xFFFFFFFF, q0, o);
            s1 += __shfl_xor_sync(0xFFFFFFFF, s1, o);
            q1 += __shfl_xor_sync(0xFFFFFFFF, q1, o);
        }
        if (lane < 4) {
            atomicAdd(&g_sum[n], s0);
            atomicAdd(&g_sum2[n], q0);
            atomicAdd(&g_sum[n + 1], s1);
            atomicAdd(&g_sum2[n + 1], q1);
        }
    }
}

// ---------------- BN finalize + apply ---------------------------------------
__global__ void bn_finalize(const float* __restrict__ gamma,
                            const float* __restrict__ beta) {
    int o = threadIdx.x;
    float mean = g_sum[o] * (1.f / 16384.f);
    float var  = g_sum2[o] * (1.f / 16384.f) - mean * mean;
    float inv  = gamma[o] * rsqrtf(var + 1e-5f);
    g_scale[o] = inv;
    g_shift[o] = beta[o] - mean * inv;
}

__global__ void bn_apply(float* __restrict__ out) {
    int t = blockIdx.x * 256 + threadIdx.x;
    int o = (t >> 10) & 255;
    float4 v = ((const float4*)g_raw)[t];
    float sc = g_scale[o], sf = g_shift[o];
    float4 r;
    r.x = fmaxf(v.x * sc + sf, 0.f);
    r.y = fmaxf(v.y * sc + sf, 0.f);
    r.z = fmaxf(v.z * sc + sf, 0.f);
    r.w = fmaxf(v.w * sc + sf, 0.f);
    ((float4*)out)[t] = r;
}

// ---------------- launch ----------------
extern "C" void kernel_launch(void* const* d_in, const int* in_sizes, int n_in,
                              void* d_out, int out_size) {
    const float* x      = (const float*)d_in[0];
    const float* w_off  = (const float*)d_in[1];
    const float* b_off  = (const float*)d_in[2];
    const float* w_conv = (const float*)d_in[3];
    const float* gamma  = (const float*)d_in[4];
    const float* beta   = (const float*)d_in[5];
    float* out = (float*)d_out;

    cudaFuncSetAttribute(gemm_main,
                         cudaFuncAttributeMaxDynamicSharedMemorySize, SMEM_GEMM);

    zero_pad_xT<<<(BB * 260 * 32 + 255) / 256, 256>>>();
    prep_xhT<<<dim3(BB * HH, CI / 64), 256>>>(x);
    prep_wB<<<(NCHUNK * 4096) / 256, 256>>>(w_conv);
    prep_wOffB<<<(NCHUNK * 384 + 255) / 256, 256>>>(w_off);
    zero_stats<<<1, 256>>>();
    offset_gemm<<<MTOT / 128, 128>>>(b_off);
    tab_kernel<<<(9 * MTOT) / 256, 256>>>();
    gather_A_kernel<<<dim3(MTOT / 128, 9), 256>>>();
    gemm_main<<<dim3(MTOT / 128, 2), 256, SMEM_GEMM>>>();
    bn_finalize<<<1, 256>>>(gamma, beta);
    bn_apply<<<(BB * CO * HW / 4) / 256, 256>>>(out);
}

// round 9
// speedup vs baseline: 1.2711x; 1.0830x over previous
#include <cuda_runtime.h>
#include <cuda_fp16.h>
#include <cstdint>

#define BB 4
#define CI 256
#define CO 256
#define HH 64
#define WW 64
#define HW 4096
#define KD 2304          // CI * 9
#define MTOT 16384
#define KC 32
#define NCHUNK 72        // KD / KC
#define PP 4356          // 66*66 padded pixels

// ---------------- scratch ----------------
__device__ __align__(16) uint32_t g_wB[NCHUNK * 4096];     // frag-ordered fp16 B (main)
__device__ __align__(16) uint32_t g_wOffB[NCHUNK * 384];   // frag-ordered fp16 B (offset)
__device__ __align__(16) uint32_t g_A[288 * MTOT * 4];     // sampled A fp16
__device__ __align__(16) __half g_xh[BB * CI * HW];        // fp16 x, (c, hw)
__device__ __align__(16) __half g_xTp[BB * PP * CI];       // fp16 x, padded transposed
__device__ __align__(16) ushort4 g_tidx[9 * MTOT];         // bilinear corner indices
__device__ __align__(16) float4  g_twts[9 * MTOT];         // bilinear corner weights
__device__ __align__(16) float g_raw[BB * CO * HW];
__device__ float g_sum[CO];
__device__ float g_sum2[CO];
__device__ float g_scale[CO];
__device__ float g_shift[CO];

// ---------------- helpers ----------------
__device__ __forceinline__ uint32_t smem_u32(const void* p) {
    uint32_t a;
    asm("{ .reg .u64 t; cvta.to.shared.u64 t, %1; cvt.u32.u64 %0, t; }" : "=r"(a) : "l"(p));
    return a;
}
__device__ __forceinline__ uint32_t pack_h2(float lo, float hi) {
    __half2 h = __floats2half2_rn(lo, hi);
    return *(uint32_t*)&h;
}
__device__ __forceinline__ void mma_f16(float* d, const uint32_t* a,
                                        uint32_t b0, uint32_t b1) {
    asm volatile(
        "mma.sync.aligned.m16n8k16.row.col.f32.f16.f16.f32 "
        "{%0,%1,%2,%3}, {%4,%5,%6,%7}, {%8,%9}, {%0,%1,%2,%3};"
        : "+f"(d[0]), "+f"(d[1]), "+f"(d[2]), "+f"(d[3])
        : "r"(a[0]), "r"(a[1]), "r"(a[2]), "r"(a[3]), "r"(b0), "r"(b1));
}
__device__ __forceinline__ void cp_async16(uint32_t saddr, const void* gaddr) {
    asm volatile("cp.async.cg.shared.global [%0], [%1], 16;" :: "r"(saddr), "l"(gaddr));
}

// bilinear table construction for one (pixel, tap)
__device__ __forceinline__ void make_tab(int b, int hw, int k, float offy, float offx) {
    int h = hw >> 6, w = hw & 63;
    int k3 = k / 3;
    float py = (float)(h + k3 - 1) + offy;
    float px = (float)(w + (k - k3 * 3) - 1) + offx;
    float fy0 = floorf(py), fx0 = floorf(px);
    float wy1 = py - fy0, wx1 = px - fx0;
    float wy0 = 1.f - wy1, wx0 = 1.f - wx1;
    int iy0 = (int)fy0, ix0 = (int)fx0;
    int iy1 = iy0 + 1, ix1 = ix0 + 1;
    float vy0 = (iy0 >= 0 && iy0 < HH) ? 1.f : 0.f;
    float vy1 = (iy1 >= 0 && iy1 < HH) ? 1.f : 0.f;
    float vx0 = (ix0 >= 0 && ix0 < WW) ? 1.f : 0.f;
    float vx1 = (ix1 >= 0 && ix1 < WW) ? 1.f : 0.f;
    int cy0 = min(max(iy0, 0), HH - 1), cy1 = min(max(iy1, 0), HH - 1);
    int cx0 = min(max(ix0, 0), WW - 1), cx1 = min(max(ix1, 0), WW - 1);
    ushort4 gi;
    gi.x = (unsigned short)(cy0 * WW + cx0);
    gi.y = (unsigned short)(cy0 * WW + cx1);
    gi.z = (unsigned short)(cy1 * WW + cx0);
    gi.w = (unsigned short)(cy1 * WW + cx1);
    int idx = (k << 14) + (b << 12) + hw;
    g_tidx[idx] = gi;
    g_twts[idx] = make_float4(wy0 * wx0 * vy0 * vx0,
                              wy0 * wx1 * vy0 * vx1,
                              wy1 * wx0 * vy1 * vx0,
                              wy1 * wx1 * vy1 * vx1);
}

// ---------------- kernel: merged prep (wB / pad / wOffB / stats) -----------
#define N_WB   (NCHUNK * 4096)          // 294912
#define N_PAD  (BB * 260 * 32)          // 33280
#define N_WOFF (NCHUNK * 384)           // 27648
#define N_MISC (N_WB + N_PAD + N_WOFF + 256)   // 356096 = 1391*256

__global__ void prep_misc(const float* __restrict__ w_conv,
                          const float* __restrict__ w_off) {
    int idx = blockIdx.x * 256 + threadIdx.x;
    if (idx < N_WB) {
        int kt = idx >> 12;
        int r  = idx & 4095;
        int k16  = r >> 11;
        int np   = (r >> 7) & 15;
        int lane = (r >> 2) & 31;
        int w    = r & 3;
        int g = lane >> 2, tg = lane & 3;
        int nt = np * 2 + (w >> 1);
        int h  = w & 1;
        int n  = nt * 8 + g;
        int ck = kt * KC + k16 * 16 + h * 8 + 2 * tg;
        g_wB[idx] = pack_h2(w_conv[n * KD + ck], w_conv[n * KD + ck + 1]);
        return;
    }
    idx -= N_WB;
    if (idx < N_PAD) {
        int q = idx & 31;
        int r = (idx >> 5) % 260;
        int b = idx / (260 * 32);
        int row;
        if (r < 66)       row = r;
        else if (r < 132) row = 65 * 66 + (r - 66);
        else if (r < 196) row = (r - 132 + 1) * 66;
        else              row = (r - 196 + 1) * 66 + 65;
        ((uint4*)(g_xTp + ((size_t)b * PP + row) * CI))[q] = make_uint4(0, 0, 0, 0);
        return;
    }
    idx -= N_PAD;
    if (idx < N_WOFF) {
        int kt = idx / 384;
        int r  = idx - kt * 384;
        int k16  = r / 192;
        int nt   = (r / 64) % 3;
        int lane = (r >> 1) & 31;
        int h    = r & 1;
        int g = lane >> 2, tg = lane & 3;
        int n = nt * 8 + g;
        int tap = kt >> 3;
        int c = (kt & 7) * 32 + k16 * 16 + h * 8 + 2 * tg;
        uint32_t val = 0;
        if (n < 18)
            val = pack_h2(w_off[n * KD + c * 9 + tap], w_off[n * KD + (c + 1) * 9 + tap]);
        g_wOffB[idx] = val;
        return;
    }
    idx -= N_WOFF;
    if (idx < 256) {
        g_sum[idx] = 0.f;
        g_sum2[idx] = 0.f;
    }
}

// ---------------- kernel: x -> fp16 (c-major) + padded transpose -----------
__global__ void prep_xhT(const float* __restrict__ x) {
    __shared__ float tile[64][65];
    int bh = blockIdx.x;
    int c0 = blockIdx.y * 64;
    int b = bh >> 6, h = bh & 63;
    int t = threadIdx.x;
    int ci = t >> 6, w = t & 63;
#pragma unroll
    for (int rep = 0; rep < 16; rep++) {
        int c = c0 + ci + rep * 4;
        size_t gi = ((size_t)(b * CI + c) << 12) + h * 64 + w;
        float v = x[gi];
        g_xh[gi] = __float2half(v);
        tile[ci + rep * 4][w] = v;
    }
    __syncthreads();
#pragma unroll
    for (int rep = 0; rep < 2; rep++) {
        int e = t + rep * 256;
        int w2 = e & 63, q = e >> 6;
        __half hv[8];
#pragma unroll
        for (int j = 0; j < 8; j++) hv[j] = __float2half(tile[q * 8 + j][w2]);
        size_t dst = ((size_t)b * PP + (h + 1) * 66 + (w2 + 1)) * CI + c0 + q * 8;
        *(uint4*)(g_xTp + dst) = *(uint4*)hv;
    }
}

// ---------------- kernel: offset conv GEMM + fused bilinear tables ---------
// M-tile 64, N=24, K=2304 (tap-major), 128 threads, 3-stage, grid 256.
__global__ void __launch_bounds__(128)
offset_gemm(const float* __restrict__ b_off) {
    __shared__ __align__(16) char As[3 * 4096];
    __shared__ __align__(16) char Bs[3 * 1536];
    const uint32_t Ab0 = smem_u32(As);
    const uint32_t Bb0 = smem_u32(Bs);
    const int t = threadIdx.x;
    const int lane = t & 31;
    const int wm = t >> 5;
    const int g = lane >> 2;
    const int tg = lane & 3;
    const int m0 = blockIdx.x << 6;
    const int b  = m0 >> 12;

    // A-load mapping: row ar (0..63), part (0/1) -> 2 cp16 each
    const int ar = t & 63;
    const int part = t >> 6;
    const int hw_a = (m0 + ar) & 4095;
    const int prow = ((hw_a >> 6) + 1) * 66 + (hw_a & 63) + 1;
    const __half* arow = g_xTp + ((size_t)b * PP + prow) * CI;
    const int rp = ar >> 1;
    const uint32_t dstA_base = rp * 128;

    auto issue = [&](int kt, int s) {
        int tap = kt >> 3;
        int shift = (tap / 3 - 1) * 66 + (tap % 3 - 1);
        const __half* src = arow + (size_t)shift * CI + (kt & 7) * 32;
#pragma unroll
        for (int qq = 0; qq < 2; qq++) {
            int q = part * 2 + qq;
            uint32_t cc = ((ar & 1) << 2) + q;
            cp_async16(Ab0 + s * 4096 + dstA_base + ((cc ^ (rp & 7)) << 4), src + q * 8);
        }
        if (t < 96)
            cp_async16(Bb0 + s * 1536 + t * 16, g_wOffB + kt * 384 + t * 4);
        asm volatile("cp.async.commit_group;" ::: "memory");
    };

    float acc[3][4];
#pragma unroll
    for (int nt = 0; nt < 3; nt++)
#pragma unroll
        for (int r = 0; r < 4; r++) acc[nt][r] = 0.f;

    auto compute = [&](int s) {
        const uint32_t Ab = Ab0 + s * 4096;
        const uint32_t Bb = Bb0 + s * 1536;
#pragma unroll
        for (int k16 = 0; k16 < 2; k16++) {
            uint32_t a[4];
            {
                int mr = wm * 16;
                int tt = lane >> 3, r = lane & 7;
                int mrow = mr + ((tt & 1) << 3) + r;
                int rp2 = mrow >> 1;
                int cc = ((mrow & 1) << 2) + (k16 << 1) + (tt >> 1);
                uint32_t addr = Ab + rp2 * 128 + ((cc ^ (rp2 & 7)) << 4);
                asm volatile(
                    "ldmatrix.sync.aligned.m8n8.x4.shared.b16 {%0,%1,%2,%3}, [%4];"
                    : "=r"(a[0]), "=r"(a[1]), "=r"(a[2]), "=r"(a[3])
                    : "r"(addr));
            }
#pragma unroll
            for (int nt = 0; nt < 3; nt++) {
                uint32_t b0, b1;
                uint32_t addr = Bb + ((k16 * 3 + nt) * 64 + lane * 2) * 4;
                asm volatile("ld.shared.v2.u32 {%0,%1}, [%2];"
                             : "=r"(b0), "=r"(b1) : "r"(addr));
                mma_f16(acc[nt], a, b0, b1);
            }
        }
    };

    issue(0, 0);
    issue(1, 1);
    asm volatile("cp.async.wait_group 1;" ::: "memory");
    __syncthreads();

    for (int kt = 0; kt < NCHUNK; kt++) {
        compute(kt % 3);
        if (kt + 2 < NCHUNK) {
            issue(kt + 2, (kt + 2) % 3);
            asm volatile("cp.async.wait_group 1;" ::: "memory");
        } else {
            asm volatile("cp.async.wait_group 0;" ::: "memory");
        }
        __syncthreads();
    }

    // fused epilogue: build bilinear tables directly from offsets
#pragma unroll
    for (int nt = 0; nt < 3; nt++) {
        int k = nt * 4 + tg;
        if (k < 9) {
            float by0 = b_off[2 * k];
            float by1 = b_off[2 * k + 1];
            int hw0 = (m0 & 4095) + wm * 16 + g;
            make_tab(b, hw0,     k, acc[nt][0] + by0, acc[nt][1] + by1);
            make_tab(b, hw0 + 8, k, acc[nt][2] + by0, acc[nt][3] + by1);
        }
    }
}

// ---------------- kernel: deformable gather (fp16 x) -> fp16 A -------------
__global__ void __launch_bounds__(256) gather_A_kernel() {
    __shared__ __align__(16) ushort4 gidx[9 * 128];
    __shared__ __align__(16) float4  gwts[9 * 128];
    const int tid = threadIdx.x;
    const int m0 = blockIdx.x << 7;
    const int b  = m0 >> 12;
    const __half* xb = g_xh + ((size_t)b * CI << 12);

    for (int e = tid; e < 9 * 128; e += 256) {
        int k  = e >> 7;
        int mm = e & 127;
        gidx[e] = g_tidx[(k << 14) + m0 + mm];
        gwts[e] = g_twts[(k << 14) + m0 + mm];
    }
    __syncthreads();

    const int mm = tid & 127;
    const int ch = tid >> 7;
    const int kb0 = blockIdx.y * 256;

#pragma unroll 2
    for (int it = 0; it < 16; it++) {
        int kc_in = ch + it * 2;
        int ckb = kb0 + kc_in * 8;
        float v[8];
#pragma unroll
        for (int s = 0; s < 8; s++) {
            int ck = ckb + s;
            int c = ck / 9;
            int tap = ck - c * 9;
            ushort4 gi = gidx[tap * 128 + mm];
            float4  gw = gwts[tap * 128 + mm];
            const __half* xc = xb + ((size_t)c << 12);
            v[s] = gw.x * __half2float(__ldg(xc + gi.x))
                 + gw.y * __half2float(__ldg(xc + gi.y))
                 + gw.z * __half2float(__ldg(xc + gi.z))
                 + gw.w * __half2float(__ldg(xc + gi.w));
        }
        uint4 wv;
        wv.x = pack_h2(v[0], v[1]);
        wv.y = pack_h2(v[2], v[3]);
        wv.z = pack_h2(v[4], v[5]);
        wv.w = pack_h2(v[6], v[7]);
        int kc = (kb0 >> 3) + kc_in;
        *(uint4*)(g_A + ((size_t)kc * MTOT + m0 + mm) * 4) = wv;
    }
}

// ---------------- kernel: pipelined fp16 HMMA GEMM -------------------------
#define ST_A 8192
#define ST_B 8192
#define OFF_A 0
#define OFF_B (3 * ST_A)
#define SMEM_GEMM (3 * ST_A + 3 * ST_B)     // 49152

__global__ void __launch_bounds__(256, 2)
gemm_main() {
    extern __shared__ char smem[];
    const uint32_t sb = smem_u32(smem);
    const int tid  = threadIdx.x;
    const int lane = tid & 31;
    const int wid  = tid >> 5;
    const int g  = lane >> 2;
    const int tg = lane & 3;
    const int wm = wid & 3;
    const int wn = wid >> 2;
    const int m0 = blockIdx.x << 7;
    const int by = blockIdx.y;
    const int b  = m0 >> 12;

    const int cm   = tid & 127;
    const int ckl0 = tid >> 7;

    auto issue = [&](int kt, int s) {
#pragma unroll
        for (int q = 0; q < 2; q++) {
            int ckl = ckl0 + q * 2;
            uint32_t dstA = (uint32_t)((cm >> 1) * 128
                         + (((((cm & 1) << 2) + ckl) ^ ((cm >> 1) & 7)) << 4));
            cp_async16(sb + OFF_A + s * ST_A + dstA,
                       g_A + ((size_t)(kt * 4 + ckl) * MTOT + m0 + cm) * 4);
        }
        const float4* wb4 = (const float4*)g_wB;
#pragma unroll
        for (int r = 0; r < 2; r++) {
            int idx = r * 256 + tid;
            int k16 = idx >> 8;
            int npl = (idx >> 5) & 7;
            int ln  = idx & 31;
            cp_async16(sb + OFF_B + s * ST_B + idx * 16,
                       wb4 + (size_t)kt * 1024 + k16 * 512 + (8 * by + npl) * 32 + ln);
        }
        asm volatile("cp.async.commit_group;" ::: "memory");
    };

    float acc[2][8][4];
#pragma unroll
    for (int mt = 0; mt < 2; mt++)
#pragma unroll
        for (int nt = 0; nt < 8; nt++)
#pragma unroll
            for (int r = 0; r < 4; r++) acc[mt][nt][r] = 0.f;

    auto compute = [&](int s) {
        const uint32_t Ab = sb + OFF_A + s * ST_A;
        const uint32_t Bb = sb + OFF_B + s * ST_B;
#pragma unroll
        for (int k16 = 0; k16 < 2; k16++) {
            uint32_t a[2][4];
#pragma unroll
            for (int mt = 0; mt < 2; mt++) {
                int mr = wm * 32 + mt * 16;
                int t = lane >> 3, r = lane & 7;
                int mrow = mr + ((t & 1) << 3) + r;
                int rp = mrow >> 1;
                int cc = ((mrow & 1) << 2) + (k16 << 1) + (t >> 1);
                uint32_t addr = Ab + rp * 128 + ((cc ^ (rp & 7)) << 4);
                asm volatile(
                    "ldmatrix.sync.aligned.m8n8.x4.shared.b16 {%0,%1,%2,%3}, [%4];"
                    : "=r"(a[mt][0]), "=r"(a[mt][1]), "=r"(a[mt][2]), "=r"(a[mt][3])
                    : "r"(addr));
            }
#pragma unroll
            for (int j = 0; j < 4; j++) {
                uint32_t b0, b1, b2, b3;
                uint32_t addr = Bb + (((k16 * 8) + wn * 4 + j) * 32 + lane) * 16;
                asm volatile("ld.shared.v4.u32 {%0,%1,%2,%3}, [%4];"
                             : "=r"(b0), "=r"(b1), "=r"(b2), "=r"(b3) : "r"(addr));
                mma_f16(acc[0][2 * j],     a[0], b0, b1);
                mma_f16(acc[1][2 * j],     a[1], b0, b1);
                mma_f16(acc[0][2 * j + 1], a[0], b2, b3);
                mma_f16(acc[1][2 * j + 1], a[1], b2, b3);
            }
        }
    };

    issue(0, 0);
    issue(1, 1);
    asm volatile("cp.async.wait_group 1;" ::: "memory");
    __syncthreads();

    for (int kt = 0; kt < NCHUNK; kt++) {
        compute(kt % 3);
        if (kt + 2 < NCHUNK) {
            issue(kt + 2, (kt + 2) % 3);
            asm volatile("cp.async.wait_group 1;" ::: "memory");
        } else {
            asm volatile("cp.async.wait_group 0;" ::: "memory");
        }
        __syncthreads();
    }

    const int hwb = (m0 & 4095);
#pragma unroll
    for (int nt = 0; nt < 8; nt++) {
        int n = by * 128 + wn * 64 + nt * 8 + 2 * tg;
        float* p0 = g_raw + ((size_t)(b * CO + n) << 12);
        float* p1 = p0 + HW;
        float s0 = 0.f, q0 = 0.f, s1 = 0.f, q1 = 0.f;
#pragma unroll
        for (int mt = 0; mt < 2; mt++) {
            int hw0 = hwb + wm * 32 + mt * 16 + g;
            float d0 = acc[mt][nt][0], d1 = acc[mt][nt][1];
            float d2 = acc[mt][nt][2], d3 = acc[mt][nt][3];
            p0[hw0]     = d0;
            p1[hw0]     = d1;
            p0[hw0 + 8] = d2;
            p1[hw0 + 8] = d3;
            s0 += d0 + d2;  q0 += d0 * d0 + d2 * d2;
            s1 += d1 + d3;  q1 += d1 * d1 + d3 * d3;
        }
#pragma unroll
        for (int o = 4; o < 32; o <<= 1) {
            s0 += __shfl_xor_sync(0xFFFFFFFF, s0, o);
            q0 += __shfl_xor_sync(0xFFFFFFFF, q0, o);
            s1 += __shfl_xor_sync(0xFFFFFFFF, s1, o);
            q1 += __shfl_xor_sync(0xFFFFFFFF, q1, o);
        }
        if (lane < 4) {
            atomicAdd(&g_sum[n], s0);
            atomicAdd(&g_sum2[n], q0);
            atomicAdd(&g_sum[n + 1], s1);
            atomicAdd(&g_sum2[n + 1], q1);
        }
    }
}

// ---------------- BN finalize + apply ---------------------------------------
__global__ void bn_finalize(const float* __restrict__ gamma,
                            const float* __restrict__ beta) {
    int o = threadIdx.x;
    float mean = g_sum[o] * (1.f / 16384.f);
    float var  = g_sum2[o] * (1.f / 16384.f) - mean * mean;
    float inv  = gamma[o] * rsqrtf(var + 1e-5f);
    g_scale[o] = inv;
    g_shift[o] = beta[o] - mean * inv;
}

__global__ void bn_apply(float* __restrict__ out) {
    int t = blockIdx.x * 256 + threadIdx.x;
    int o = (t >> 10) & 255;
    float4 v = ((const float4*)g_raw)[t];
    float sc = g_scale[o], sf = g_shift[o];
    float4 r;
    r.x = fmaxf(v.x * sc + sf, 0.f);
    r.y = fmaxf(v.y * sc + sf, 0.f);
    r.z = fmaxf(v.z * sc + sf, 0.f);
    r.w = fmaxf(v.w * sc + sf, 0.f);
    ((float4*)out)[t] = r;
}

// ---------------- launch ----------------
extern "C" void kernel_launch(void* const* d_in, const int* in_sizes, int n_in,
                              void* d_out, int out_size) {
    const float* x      = (const float*)d_in[0];
    const float* w_off  = (const float*)d_in[1];
    const float* b_off  = (const float*)d_in[2];
    const float* w_conv = (const float*)d_in[3];
    const float* gamma  = (const float*)d_in[4];
    const float* beta   = (const float*)d_in[5];
    float* out = (float*)d_out;

    cudaFuncSetAttribute(gemm_main,
                         cudaFuncAttributeMaxDynamicSharedMemorySize, SMEM_GEMM);

    prep_misc<<<N_MISC / 256, 256>>>(w_conv, w_off);
    prep_xhT<<<dim3(BB * HH, CI / 64), 256>>>(x);
    offset_gemm<<<MTOT / 64, 128>>>(b_off);
    gather_A_kernel<<<dim3(MTOT / 128, 9), 256>>>();
    gemm_main<<<dim3(MTOT / 128, 2), 256, SMEM_GEMM>>>();
    bn_finalize<<<1, 256>>>(gamma, beta);
    bn_apply<<<(BB * CO * HW / 4) / 256, 256>>>(out);
}

// round 10
// speedup vs baseline: 1.6529x; 1.3004x over previous
#include <cuda_runtime.h>
#include <cuda_fp16.h>
#include <cstdint>

#define BB 4
#define CI 256
#define CO 256
#define HH 64
#define WW 64
#define HW 4096
#define KD 2304          // CI * 9
#define MTOT 16384
#define KC 32
#define NCHUNK 72        // KD / KC
#define PP 4356          // 66*66 padded pixels

// ---------------- scratch ----------------
__device__ __align__(16) uint32_t g_wB[NCHUNK * 4096];     // frag-ordered fp16 B (main, tap-major k)
__device__ __align__(16) uint32_t g_wOffB[NCHUNK * 384];   // frag-ordered fp16 B (offset)
__device__ __align__(16) __half g_A[(size_t)MTOT * KD];    // sampled A fp16, [m][2304]
__device__ __align__(16) __half g_xTp[BB * PP * CI];       // fp16 x, padded transposed (hw, c)
__device__ __align__(16) ushort4 g_tidx[9 * MTOT];         // corner PADDED row indices
__device__ __align__(16) uint4   g_tw2[9 * MTOT];          // corner weights as 4x half2
__device__ __align__(16) float g_raw[BB * CO * HW];
__device__ float g_sum[CO];
__device__ float g_sum2[CO];
__device__ float g_scale[CO];
__device__ float g_shift[CO];

// ---------------- helpers ----------------
__device__ __forceinline__ uint32_t smem_u32(const void* p) {
    uint32_t a;
    asm("{ .reg .u64 t; cvta.to.shared.u64 t, %1; cvt.u32.u64 %0, t; }" : "=r"(a) : "l"(p));
    return a;
}
__device__ __forceinline__ uint32_t pack_h2(float lo, float hi) {
    __half2 h = __floats2half2_rn(lo, hi);
    return *(uint32_t*)&h;
}
__device__ __forceinline__ void mma_f16(float* d, const uint32_t* a,
                                        uint32_t b0, uint32_t b1) {
    asm volatile(
        "mma.sync.aligned.m16n8k16.row.col.f32.f16.f16.f32 "
        "{%0,%1,%2,%3}, {%4,%5,%6,%7}, {%8,%9}, {%0,%1,%2,%3};"
        : "+f"(d[0]), "+f"(d[1]), "+f"(d[2]), "+f"(d[3])
        : "r"(a[0]), "r"(a[1]), "r"(a[2]), "r"(a[3]), "r"(b0), "r"(b1));
}
__device__ __forceinline__ void cp_async16(uint32_t saddr, const void* gaddr) {
    asm volatile("cp.async.cg.shared.global [%0], [%1], 16;" :: "r"(saddr), "l"(gaddr));
}
__device__ __forceinline__ uint32_t h2dot(uint32_t c0, uint32_t c1, uint32_t c2, uint32_t c3,
                                          __half2 w0, __half2 w1, __half2 w2, __half2 w3) {
    __half2 r = __hmul2(w0, *(__half2*)&c0);
    r = __hfma2(w1, *(__half2*)&c1, r);
    r = __hfma2(w2, *(__half2*)&c2, r);
    r = __hfma2(w3, *(__half2*)&c3, r);
    return *(uint32_t*)&r;
}

// bilinear table construction for one (pixel, tap): padded indices + half2 weights
__device__ __forceinline__ void make_tab(int b, int hw, int k, float offy, float offx) {
    int h = hw >> 6, w = hw & 63;
    int k3 = k / 3;
    float py = (float)(h + k3 - 1) + offy;
    float px = (float)(w + (k - k3 * 3) - 1) + offx;
    float fy0 = floorf(py), fx0 = floorf(px);
    float wy1 = py - fy0, wx1 = px - fx0;
    float wy0 = 1.f - wy1, wx0 = 1.f - wx1;
    int iy0 = (int)fy0, ix0 = (int)fx0;
    int iy1 = iy0 + 1, ix1 = ix0 + 1;
    float vy0 = (iy0 >= 0 && iy0 < HH) ? 1.f : 0.f;
    float vy1 = (iy1 >= 0 && iy1 < HH) ? 1.f : 0.f;
    float vx0 = (ix0 >= 0 && ix0 < WW) ? 1.f : 0.f;
    float vx1 = (ix1 >= 0 && ix1 < WW) ? 1.f : 0.f;
    int cy0 = min(max(iy0, 0), HH - 1), cy1 = min(max(iy1, 0), HH - 1);
    int cx0 = min(max(ix0, 0), WW - 1), cx1 = min(max(ix1, 0), WW - 1);
    ushort4 gi;
    gi.x = (unsigned short)((cy0 + 1) * 66 + cx0 + 1);
    gi.y = (unsigned short)((cy0 + 1) * 66 + cx1 + 1);
    gi.z = (unsigned short)((cy1 + 1) * 66 + cx0 + 1);
    gi.w = (unsigned short)((cy1 + 1) * 66 + cx1 + 1);
    int idx = (k << 14) + (b << 12) + hw;
    g_tidx[idx] = gi;
    float w00 = wy0 * wx0 * vy0 * vx0;
    float w01 = wy0 * wx1 * vy0 * vx1;
    float w10 = wy1 * wx0 * vy1 * vx0;
    float w11 = wy1 * wx1 * vy1 * vx1;
    uint4 wq;
    wq.x = pack_h2(w00, w00);
    wq.y = pack_h2(w01, w01);
    wq.z = pack_h2(w10, w10);
    wq.w = pack_h2(w11, w11);
    g_tw2[idx] = wq;
}

// ---------------- kernel: merged prep (wB / pad / wOffB / stats) -----------
#define N_WB   (NCHUNK * 4096)          // 294912
#define N_PAD  (BB * 260 * 32)          // 33280
#define N_WOFF (NCHUNK * 384)           // 27648
#define N_MISC (N_WB + N_PAD + N_WOFF + 256)   // 356096 = 1391*256

__global__ void prep_misc(const float* __restrict__ w_conv,
                          const float* __restrict__ w_off) {
    int idx = blockIdx.x * 256 + threadIdx.x;
    if (idx < N_WB) {
        int kt = idx >> 12;
        int r  = idx & 4095;
        int k16  = r >> 11;
        int np   = (r >> 7) & 15;
        int lane = (r >> 2) & 31;
        int w    = r & 3;
        int g = lane >> 2, tg = lane & 3;
        int nt = np * 2 + (w >> 1);
        int h  = w & 1;
        int n  = nt * 8 + g;
        int ck = kt * KC + k16 * 16 + h * 8 + 2 * tg;   // tap-major k index
        int tap = ck >> 8;
        int c   = ck & 255;
        g_wB[idx] = pack_h2(w_conv[n * KD + c * 9 + tap],
                            w_conv[n * KD + (c + 1) * 9 + tap]);
        return;
    }
    idx -= N_WB;
    if (idx < N_PAD) {
        int q = idx & 31;
        int r = (idx >> 5) % 260;
        int b = idx / (260 * 32);
        int row;
        if (r < 66)       row = r;
        else if (r < 132) row = 65 * 66 + (r - 66);
        else if (r < 196) row = (r - 132 + 1) * 66;
        else              row = (r - 196 + 1) * 66 + 65;
        ((uint4*)(g_xTp + ((size_t)b * PP + row) * CI))[q] = make_uint4(0, 0, 0, 0);
        return;
    }
    idx -= N_PAD;
    if (idx < N_WOFF) {
        int kt = idx / 384;
        int r  = idx - kt * 384;
        int k16  = r / 192;
        int nt   = (r / 64) % 3;
        int lane = (r >> 1) & 31;
        int h    = r & 1;
        int g = lane >> 2, tg = lane & 3;
        int n = nt * 8 + g;
        int tap = kt >> 3;
        int c = (kt & 7) * 32 + k16 * 16 + h * 8 + 2 * tg;
        uint32_t val = 0;
        if (n < 18)
            val = pack_h2(w_off[n * KD + c * 9 + tap], w_off[n * KD + (c + 1) * 9 + tap]);
        g_wOffB[idx] = val;
        return;
    }
    idx -= N_WOFF;
    if (idx < 256) {
        g_sum[idx] = 0.f;
        g_sum2[idx] = 0.f;
    }
}

// ---------------- kernel: x -> padded transposed fp16 ----------------------
__global__ void prep_xhT(const float* __restrict__ x) {
    __shared__ float tile[64][65];
    int bh = blockIdx.x;
    int c0 = blockIdx.y * 64;
    int b = bh >> 6, h = bh & 63;
    int t = threadIdx.x;
    int ci = t >> 6, w = t & 63;
#pragma unroll
    for (int rep = 0; rep < 16; rep++) {
        int c = c0 + ci + rep * 4;
        tile[ci + rep * 4][w] = x[((size_t)(b * CI + c) << 12) + h * 64 + w];
    }
    __syncthreads();
#pragma unroll
    for (int rep = 0; rep < 2; rep++) {
        int e = t + rep * 256;
        int w2 = e & 63, q = e >> 6;
        __half hv[8];
#pragma unroll
        for (int j = 0; j < 8; j++) hv[j] = __float2half(tile[q * 8 + j][w2]);
        size_t dst = ((size_t)b * PP + (h + 1) * 66 + (w2 + 1)) * CI + c0 + q * 8;
        *(uint4*)(g_xTp + dst) = *(uint4*)hv;
    }
}

// ---------------- kernel: offset conv GEMM + fused bilinear tables ---------
__global__ void __launch_bounds__(128)
offset_gemm(const float* __restrict__ b_off) {
    __shared__ __align__(16) char As[3 * 4096];
    __shared__ __align__(16) char Bs[3 * 1536];
    const uint32_t Ab0 = smem_u32(As);
    const uint32_t Bb0 = smem_u32(Bs);
    const int t = threadIdx.x;
    const int lane = t & 31;
    const int wm = t >> 5;
    const int g = lane >> 2;
    const int tg = lane & 3;
    const int m0 = blockIdx.x << 6;
    const int b  = m0 >> 12;

    const int ar = t & 63;
    const int part = t >> 6;
    const int hw_a = (m0 + ar) & 4095;
    const int prow = ((hw_a >> 6) + 1) * 66 + (hw_a & 63) + 1;
    const __half* arow = g_xTp + ((size_t)b * PP + prow) * CI;
    const int rp = ar >> 1;
    const uint32_t dstA_base = rp * 128;

    auto issue = [&](int kt, int s) {
        int tap = kt >> 3;
        int shift = (tap / 3 - 1) * 66 + (tap % 3 - 1);
        const __half* src = arow + (size_t)shift * CI + (kt & 7) * 32;
#pragma unroll
        for (int qq = 0; qq < 2; qq++) {
            int q = part * 2 + qq;
            uint32_t cc = ((ar & 1) << 2) + q;
            cp_async16(Ab0 + s * 4096 + dstA_base + ((cc ^ (rp & 7)) << 4), src + q * 8);
        }
        if (t < 96)
            cp_async16(Bb0 + s * 1536 + t * 16, g_wOffB + kt * 384 + t * 4);
        asm volatile("cp.async.commit_group;" ::: "memory");
    };

    float acc[3][4];
#pragma unroll
    for (int nt = 0; nt < 3; nt++)
#pragma unroll
        for (int r = 0; r < 4; r++) acc[nt][r] = 0.f;

    auto compute = [&](int s) {
        const uint32_t Ab = Ab0 + s * 4096;
        const uint32_t Bb = Bb0 + s * 1536;
#pragma unroll
        for (int k16 = 0; k16 < 2; k16++) {
            uint32_t a[4];
            {
                int mr = wm * 16;
                int tt = lane >> 3, r = lane & 7;
                int mrow = mr + ((tt & 1) << 3) + r;
                int rp2 = mrow >> 1;
                int cc = ((mrow & 1) << 2) + (k16 << 1) + (tt >> 1);
                uint32_t addr = Ab + rp2 * 128 + ((cc ^ (rp2 & 7)) << 4);
                asm volatile(
                    "ldmatrix.sync.aligned.m8n8.x4.shared.b16 {%0,%1,%2,%3}, [%4];"
                    : "=r"(a[0]), "=r"(a[1]), "=r"(a[2]), "=r"(a[3])
                    : "r"(addr));
            }
#pragma unroll
            for (int nt = 0; nt < 3; nt++) {
                uint32_t b0, b1;
                uint32_t addr = Bb + ((k16 * 3 + nt) * 64 + lane * 2) * 4;
                asm volatile("ld.shared.v2.u32 {%0,%1}, [%2];"
                             : "=r"(b0), "=r"(b1) : "r"(addr));
                mma_f16(acc[nt], a, b0, b1);
            }
        }
    };

    issue(0, 0);
    issue(1, 1);
    asm volatile("cp.async.wait_group 1;" ::: "memory");
    __syncthreads();

    for (int kt = 0; kt < NCHUNK; kt++) {
        compute(kt % 3);
        if (kt + 2 < NCHUNK) {
            issue(kt + 2, (kt + 2) % 3);
            asm volatile("cp.async.wait_group 1;" ::: "memory");
        } else {
            asm volatile("cp.async.wait_group 0;" ::: "memory");
        }
        __syncthreads();
    }

#pragma unroll
    for (int nt = 0; nt < 3; nt++) {
        int k = nt * 4 + tg;
        if (k < 9) {
            float by0 = b_off[2 * k];
            float by1 = b_off[2 * k + 1];
            int hw0 = (m0 & 4095) + wm * 16 + g;
            make_tab(b, hw0,     k, acc[nt][0] + by0, acc[nt][1] + by1);
            make_tab(b, hw0 + 8, k, acc[nt][2] + by0, acc[nt][3] + by1);
        }
    }
}

// ---------------- kernel: channel-vector gather -> fp16 A ------------------
// warp task = one (m, tap): lanes cover 256 channels; 4 coalesced corner rows.
__global__ void __launch_bounds__(256) gather_A_kernel() {
    const int tid = threadIdx.x;
    const int lane = tid & 31;
    const int wid = tid >> 5;
    const int m0 = blockIdx.x << 5;         // 32 pixels per block
    const int b = m0 >> 12;
    const __half2* base = (const __half2*)(g_xTp + (size_t)b * PP * CI);

    const int mw = m0 + wid * 4;
#pragma unroll 1
    for (int i = 0; i < 4; i++) {
        int m = mw + i;
        __half* dstm = g_A + (size_t)m * KD + lane * 8;
#pragma unroll 3
        for (int tap = 0; tap < 9; tap++) {
            int idx = (tap << 14) + m;
            ushort4 gi = g_tidx[idx];
            uint4 wq = g_tw2[idx];
            const uint4* p0 = (const uint4*)(base + (int)gi.x * 128) + lane;
            const uint4* p1 = (const uint4*)(base + (int)gi.y * 128) + lane;
            const uint4* p2 = (const uint4*)(base + (int)gi.z * 128) + lane;
            const uint4* p3 = (const uint4*)(base + (int)gi.w * 128) + lane;
            uint4 a0 = __ldg(p0);
            uint4 a1 = __ldg(p1);
            uint4 a2 = __ldg(p2);
            uint4 a3 = __ldg(p3);
            __half2 w0 = *(__half2*)&wq.x, w1 = *(__half2*)&wq.y;
            __half2 w2 = *(__half2*)&wq.z, w3 = *(__half2*)&wq.w;
            uint4 o;
            o.x = h2dot(a0.x, a1.x, a2.x, a3.x, w0, w1, w2, w3);
            o.y = h2dot(a0.y, a1.y, a2.y, a3.y, w0, w1, w2, w3);
            o.z = h2dot(a0.z, a1.z, a2.z, a3.z, w0, w1, w2, w3);
            o.w = h2dot(a0.w, a1.w, a2.w, a3.w, w0, w1, w2, w3);
            *(uint4*)(dstm + tap * 256) = o;
        }
    }
}

// ---------------- kernel: pipelined fp16 HMMA GEMM -------------------------
#define ST_A 8192
#define ST_B 8192
#define OFF_A 0
#define OFF_B (3 * ST_A)
#define SMEM_GEMM (3 * ST_A + 3 * ST_B)     // 49152

__global__ void __launch_bounds__(256, 2)
gemm_main() {
    extern __shared__ char smem[];
    const uint32_t sb = smem_u32(smem);
    const int tid  = threadIdx.x;
    const int lane = tid & 31;
    const int wid  = tid >> 5;
    const int g  = lane >> 2;
    const int tg = lane & 3;
    const int wm = wid & 3;
    const int wn = wid >> 2;
    const int m0 = blockIdx.x << 7;
    const int by = blockIdx.y;
    const int b  = m0 >> 12;

    const int cm   = tid & 127;
    const int ckl0 = tid >> 7;

    auto issue = [&](int kt, int s) {
#pragma unroll
        for (int q = 0; q < 2; q++) {
            int ckl = ckl0 + q * 2;
            uint32_t dstA = (uint32_t)((cm >> 1) * 128
                         + (((((cm & 1) << 2) + ckl) ^ ((cm >> 1) & 7)) << 4));
            cp_async16(sb + OFF_A + s * ST_A + dstA,
                       g_A + (size_t)(m0 + cm) * KD + kt * KC + ckl * 8);
        }
        const float4* wb4 = (const float4*)g_wB;
#pragma unroll
        for (int r = 0; r < 2; r++) {
            int idx = r * 256 + tid;
            int k16 = idx >> 8;
            int npl = (idx >> 5) & 7;
            int ln  = idx & 31;
            cp_async16(sb + OFF_B + s * ST_B + idx * 16,
                       wb4 + (size_t)kt * 1024 + k16 * 512 + (8 * by + npl) * 32 + ln);
        }
        asm volatile("cp.async.commit_group;" ::: "memory");
    };

    float acc[2][8][4];
#pragma unroll
    for (int mt = 0; mt < 2; mt++)
#pragma unroll
        for (int nt = 0; nt < 8; nt++)
#pragma unroll
            for (int r = 0; r < 4; r++) acc[mt][nt][r] = 0.f;

    auto compute = [&](int s) {
        const uint32_t Ab = sb + OFF_A + s * ST_A;
        const uint32_t Bb = sb + OFF_B + s * ST_B;
#pragma unroll
        for (int k16 = 0; k16 < 2; k16++) {
            uint32_t a[2][4];
#pragma unroll
            for (int mt = 0; mt < 2; mt++) {
                int mr = wm * 32 + mt * 16;
                int t = lane >> 3, r = lane & 7;
                int mrow = mr + ((t & 1) << 3) + r;
                int rp = mrow >> 1;
                int cc = ((mrow & 1) << 2) + (k16 << 1) + (t >> 1);
                uint32_t addr = Ab + rp * 128 + ((cc ^ (rp & 7)) << 4);
                asm volatile(
                    "ldmatrix.sync.aligned.m8n8.x4.shared.b16 {%0,%1,%2,%3}, [%4];"
                    : "=r"(a[mt][0]), "=r"(a[mt][1]), "=r"(a[mt][2]), "=r"(a[mt][3])
                    : "r"(addr));
            }
#pragma unroll
            for (int j = 0; j < 4; j++) {
                uint32_t b0, b1, b2, b3;
                uint32_t addr = Bb + (((k16 * 8) + wn * 4 + j) * 32 + lane) * 16;
                asm volatile("ld.shared.v4.u32 {%0,%1,%2,%3}, [%4];"
                             : "=r"(b0), "=r"(b1), "=r"(b2), "=r"(b3) : "r"(addr));
                mma_f16(acc[0][2 * j],     a[0], b0, b1);
                mma_f16(acc[1][2 * j],     a[1], b0, b1);
                mma_f16(acc[0][2 * j + 1], a[0], b2, b3);
                mma_f16(acc[1][2 * j + 1], a[1], b2, b3);
            }
        }
    };

    issue(0, 0);
    issue(1, 1);
    asm volatile("cp.async.wait_group 1;" ::: "memory");
    __syncthreads();

    for (int kt = 0; kt < NCHUNK; kt++) {
        compute(kt % 3);
        if (kt + 2 < NCHUNK) {
            issue(kt + 2, (kt + 2) % 3);
            asm volatile("cp.async.wait_group 1;" ::: "memory");
        } else {
            asm volatile("cp.async.wait_group 0;" ::: "memory");
        }
        __syncthreads();
    }

    const int hwb = (m0 & 4095);
#pragma unroll
    for (int nt = 0; nt < 8; nt++) {
        int n = by * 128 + wn * 64 + nt * 8 + 2 * tg;
        float* p0 = g_raw + ((size_t)(b * CO + n) << 12);
        float* p1 = p0 + HW;
        float s0 = 0.f, q0 = 0.f, s1 = 0.f, q1 = 0.f;
#pragma unroll
        for (int mt = 0; mt < 2; mt++) {
            int hw0 = hwb + wm * 32 + mt * 16 + g;
            float d0 = acc[mt][nt][0], d1 = acc[mt][nt][1];
            float d2 = acc[mt][nt][2], d3 = acc[mt][nt][3];
            p0[hw0]     = d0;
            p1[hw0]     = d1;
            p0[hw0 + 8] = d2;
            p1[hw0 + 8] = d3;
            s0 += d0 + d2;  q0 += d0 * d0 + d2 * d2;
            s1 += d1 + d3;  q1 += d1 * d1 + d3 * d3;
        }
#pragma unroll
        for (int o = 4; o < 32; o <<= 1) {
            s0 += __shfl_xor_sync(0xFFFFFFFF, s0, o);
            q0 += __shfl_xor_sync(0xFFFFFFFF, q0, o);
            s1 += __shfl_xor_sync(0xFFFFFFFF, s1, o);
            q1 += __shfl_xor_sync(0xFFFFFFFF, q1, o);
        }
        if (lane < 4) {
            atomicAdd(&g_sum[n], s0);
            atomicAdd(&g_sum2[n], q0);
            atomicAdd(&g_sum[n + 1], s1);
            atomicAdd(&g_sum2[n + 1], q1);
        }
    }
}

// ---------------- BN finalize + apply ---------------------------------------
__global__ void bn_finalize(const float* __restrict__ gamma,
                            const float* __restrict__ beta) {
    int o = threadIdx.x;
    float mean = g_sum[o] * (1.f / 16384.f);
    float var  = g_sum2[o] * (1.f / 16384.f) - mean * mean;
    float inv  = gamma[o] * rsqrtf(var + 1e-5f);
    g_scale[o] = inv;
    g_shift[o] = beta[o] - mean * inv;
}

__global__ void bn_apply(float* __restrict__ out) {
    int t = blockIdx.x * 256 + threadIdx.x;
    int o = (t >> 10) & 255;
    float4 v = ((const float4*)g_raw)[t];
    float sc = g_scale[o], sf = g_shift[o];
    float4 r;
    r.x = fmaxf(v.x * sc + sf, 0.f);
    r.y = fmaxf(v.y * sc + sf, 0.f);
    r.z = fmaxf(v.z * sc + sf, 0.f);
    r.w = fmaxf(v.w * sc + sf, 0.f);
    ((float4*)out)[t] = r;
}

// ---------------- launch ----------------
extern "C" void kernel_launch(void* const* d_in, const int* in_sizes, int n_in,
                              void* d_out, int out_size) {
    const float* x      = (const float*)d_in[0];
    const float* w_off  = (const float*)d_in[1];
    const float* b_off  = (const float*)d_in[2];
    const float* w_conv = (const float*)d_in[3];
    const float* gamma  = (const float*)d_in[4];
    const float* beta   = (const float*)d_in[5];
    float* out = (float*)d_out;

    cudaFuncSetAttribute(gemm_main,
                         cudaFuncAttributeMaxDynamicSharedMemorySize, SMEM_GEMM);

    prep_misc<<<N_MISC / 256, 256>>>(w_conv, w_off);
    prep_xhT<<<dim3(BB * HH, CI / 64), 256>>>(x);
    offset_gemm<<<MTOT / 64, 128>>>(b_off);
    gather_A_kernel<<<MTOT / 32, 256>>>();
    gemm_main<<<dim3(MTOT / 128, 2), 256, SMEM_GEMM>>>();
    bn_finalize<<<1, 256>>>(gamma, beta);
    bn_apply<<<(BB * CO * HW / 4) / 256, 256>>>(out);
}

// round 11
// speedup vs baseline: 1.6911x; 1.0231x over previous
#include <cuda_runtime.h>
#include <cuda_fp16.h>
#include <cstdint>

#define BB 4
#define CI 256
#define CO 256
#define HH 64
#define WW 64
#define HW 4096
#define KD 2304          // CI * 9
#define MTOT 16384
#define NCHUNK 72        // KD / 32  (B packing granularity)
#define NKT2 36          // KD / 64  (gemm main-loop chunks)
#define PP 4356          // 66*66 padded pixels

// ---------------- scratch ----------------
__device__ __align__(16) uint32_t g_wB[NCHUNK * 4096];     // frag-ordered fp16 B (main, tap-major k)
__device__ __align__(16) uint32_t g_wOffB[NCHUNK * 384];   // frag-ordered fp16 B (offset)
__device__ __align__(16) __half g_A[(size_t)MTOT * KD];    // sampled A fp16, [m][2304]
__device__ __align__(16) __half g_xTp[BB * PP * CI];       // fp16 x, padded transposed (hw, c)
__device__ __align__(16) ushort4 g_tidx[9 * MTOT];         // corner PADDED row indices
__device__ __align__(16) uint4   g_tw2[9 * MTOT];          // corner weights as 4x half2
__device__ __align__(16) float g_raw[BB * CO * HW];
__device__ float g_sum[CO];
__device__ float g_sum2[CO];

// ---------------- helpers ----------------
__device__ __forceinline__ uint32_t smem_u32(const void* p) {
    uint32_t a;
    asm("{ .reg .u64 t; cvta.to.shared.u64 t, %1; cvt.u32.u64 %0, t; }" : "=r"(a) : "l"(p));
    return a;
}
__device__ __forceinline__ uint32_t pack_h2(float lo, float hi) {
    __half2 h = __floats2half2_rn(lo, hi);
    return *(uint32_t*)&h;
}
__device__ __forceinline__ void mma_f16(float* d, const uint32_t* a,
                                        uint32_t b0, uint32_t b1) {
    asm volatile(
        "mma.sync.aligned.m16n8k16.row.col.f32.f16.f16.f32 "
        "{%0,%1,%2,%3}, {%4,%5,%6,%7}, {%8,%9}, {%0,%1,%2,%3};"
        : "+f"(d[0]), "+f"(d[1]), "+f"(d[2]), "+f"(d[3])
        : "r"(a[0]), "r"(a[1]), "r"(a[2]), "r"(a[3]), "r"(b0), "r"(b1));
}
__device__ __forceinline__ void cp_async16(uint32_t saddr, const void* gaddr) {
    asm volatile("cp.async.cg.shared.global [%0], [%1], 16;" :: "r"(saddr), "l"(gaddr));
}
__device__ __forceinline__ uint32_t h2dot(uint32_t c0, uint32_t c1, uint32_t c2, uint32_t c3,
                                          __half2 w0, __half2 w1, __half2 w2, __half2 w3) {
    __half2 r = __hmul2(w0, *(__half2*)&c0);
    r = __hfma2(w1, *(__half2*)&c1, r);
    r = __hfma2(w2, *(__half2*)&c2, r);
    r = __hfma2(w3, *(__half2*)&c3, r);
    return *(uint32_t*)&r;
}

// bilinear table construction for one (pixel, tap)
__device__ __forceinline__ void make_tab(int b, int hw, int k, float offy, float offx) {
    int h = hw >> 6, w = hw & 63;
    int k3 = k / 3;
    float py = (float)(h + k3 - 1) + offy;
    float px = (float)(w + (k - k3 * 3) - 1) + offx;
    float fy0 = floorf(py), fx0 = floorf(px);
    float wy1 = py - fy0, wx1 = px - fx0;
    float wy0 = 1.f - wy1, wx0 = 1.f - wx1;
    int iy0 = (int)fy0, ix0 = (int)fx0;
    int iy1 = iy0 + 1, ix1 = ix0 + 1;
    float vy0 = (iy0 >= 0 && iy0 < HH) ? 1.f : 0.f;
    float vy1 = (iy1 >= 0 && iy1 < HH) ? 1.f : 0.f;
    float vx0 = (ix0 >= 0 && ix0 < WW) ? 1.f : 0.f;
    float vx1 = (ix1 >= 0 && ix1 < WW) ? 1.f : 0.f;
    int cy0 = min(max(iy0, 0), HH - 1), cy1 = min(max(iy1, 0), HH - 1);
    int cx0 = min(max(ix0, 0), WW - 1), cx1 = min(max(ix1, 0), WW - 1);
    ushort4 gi;
    gi.x = (unsigned short)((cy0 + 1) * 66 + cx0 + 1);
    gi.y = (unsigned short)((cy0 + 1) * 66 + cx1 + 1);
    gi.z = (unsigned short)((cy1 + 1) * 66 + cx0 + 1);
    gi.w = (unsigned short)((cy1 + 1) * 66 + cx1 + 1);
    int idx = (k << 14) + (b << 12) + hw;
    g_tidx[idx] = gi;
    float w00 = wy0 * wx0 * vy0 * vx0;
    float w01 = wy0 * wx1 * vy0 * vx1;
    float w10 = wy1 * wx0 * vy1 * vx0;
    float w11 = wy1 * wx1 * vy1 * vx1;
    uint4 wq;
    wq.x = pack_h2(w00, w00);
    wq.y = pack_h2(w01, w01);
    wq.z = pack_h2(w10, w10);
    wq.w = pack_h2(w11, w11);
    g_tw2[idx] = wq;
}

// ---------------- kernel: unified prep (xhT + wB + pad + wOffB + stats) ----
#define N_WB   (NCHUNK * 4096)
#define N_PAD  (BB * 260 * 32)
#define N_WOFF (NCHUNK * 384)
#define N_MISC (N_WB + N_PAD + N_WOFF + 256)    // 356096 = 1391*256
#define NB_XHT (BB * HH * 4)                    // 1024 transpose blocks
#define NB_PREP (NB_XHT + N_MISC / 256)         // 2415

__global__ void prep_all(const float* __restrict__ x,
                         const float* __restrict__ w_conv,
                         const float* __restrict__ w_off) {
    __shared__ float tile[64][65];
    int blk = blockIdx.x;
    int t = threadIdx.x;
    if (blk < NB_XHT) {
        int bh = blk & 255;
        int c0 = (blk >> 8) * 64;
        int b = bh >> 6, h = bh & 63;
        int ci = t >> 6, w = t & 63;
#pragma unroll
        for (int rep = 0; rep < 16; rep++) {
            int c = c0 + ci + rep * 4;
            tile[ci + rep * 4][w] = x[((size_t)(b * CI + c) << 12) + h * 64 + w];
        }
        __syncthreads();
#pragma unroll
        for (int rep = 0; rep < 2; rep++) {
            int e = t + rep * 256;
            int w2 = e & 63, q = e >> 6;
            __half hv[8];
#pragma unroll
            for (int j = 0; j < 8; j++) hv[j] = __float2half(tile[q * 8 + j][w2]);
            size_t dst = ((size_t)b * PP + (h + 1) * 66 + (w2 + 1)) * CI + c0 + q * 8;
            *(uint4*)(g_xTp + dst) = *(uint4*)hv;
        }
        return;
    }
    int idx = (blk - NB_XHT) * 256 + t;
    if (idx < N_WB) {
        int kt = idx >> 12;
        int r  = idx & 4095;
        int k16  = r >> 11;
        int np   = (r >> 7) & 15;
        int lane = (r >> 2) & 31;
        int w    = r & 3;
        int g = lane >> 2, tg = lane & 3;
        int nt = np * 2 + (w >> 1);
        int h  = w & 1;
        int n  = nt * 8 + g;
        int ck = kt * 32 + k16 * 16 + h * 8 + 2 * tg;   // tap-major k index
        int tap = ck >> 8;
        int c   = ck & 255;
        g_wB[idx] = pack_h2(w_conv[n * KD + c * 9 + tap],
                            w_conv[n * KD + (c + 1) * 9 + tap]);
        return;
    }
    idx -= N_WB;
    if (idx < N_PAD) {
        int q = idx & 31;
        int r = (idx >> 5) % 260;
        int b = idx / (260 * 32);
        int row;
        if (r < 66)       row = r;
        else if (r < 132) row = 65 * 66 + (r - 66);
        else if (r < 196) row = (r - 132 + 1) * 66;
        else              row = (r - 196 + 1) * 66 + 65;
        ((uint4*)(g_xTp + ((size_t)b * PP + row) * CI))[q] = make_uint4(0, 0, 0, 0);
        return;
    }
    idx -= N_PAD;
    if (idx < N_WOFF) {
        int kt = idx / 384;
        int r  = idx - kt * 384;
        int k16  = r / 192;
        int nt   = (r / 64) % 3;
        int lane = (r >> 1) & 31;
        int h    = r & 1;
        int g = lane >> 2, tg = lane & 3;
        int n = nt * 8 + g;
        int tap = kt >> 3;
        int c = (kt & 7) * 32 + k16 * 16 + h * 8 + 2 * tg;
        uint32_t val = 0;
        if (n < 18)
            val = pack_h2(w_off[n * KD + c * 9 + tap], w_off[n * KD + (c + 1) * 9 + tap]);
        g_wOffB[idx] = val;
        return;
    }
    idx -= N_WOFF;
    if (idx < 256) {
        g_sum[idx] = 0.f;
        g_sum2[idx] = 0.f;
    }
}

// ---------------- kernel: offset conv GEMM + fused bilinear tables ---------
__global__ void __launch_bounds__(128)
offset_gemm(const float* __restrict__ b_off) {
    __shared__ __align__(16) char As[3 * 4096];
    __shared__ __align__(16) char Bs[3 * 1536];
    const uint32_t Ab0 = smem_u32(As);
    const uint32_t Bb0 = smem_u32(Bs);
    const int t = threadIdx.x;
    const int lane = t & 31;
    const int wm = t >> 5;
    const int g = lane >> 2;
    const int tg = lane & 3;
    const int m0 = blockIdx.x << 6;
    const int b  = m0 >> 12;

    const int ar = t & 63;
    const int part = t >> 6;
    const int hw_a = (m0 + ar) & 4095;
    const int prow = ((hw_a >> 6) + 1) * 66 + (hw_a & 63) + 1;
    const __half* arow = g_xTp + ((size_t)b * PP + prow) * CI;
    const int rp = ar >> 1;
    const uint32_t dstA_base = rp * 128;

    auto issue = [&](int kt, int s) {
        int tap = kt >> 3;
        int shift = (tap / 3 - 1) * 66 + (tap % 3 - 1);
        const __half* src = arow + (size_t)shift * CI + (kt & 7) * 32;
#pragma unroll
        for (int qq = 0; qq < 2; qq++) {
            int q = part * 2 + qq;
            uint32_t cc = ((ar & 1) << 2) + q;
            cp_async16(Ab0 + s * 4096 + dstA_base + ((cc ^ (rp & 7)) << 4), src + q * 8);
        }
        if (t < 96)
            cp_async16(Bb0 + s * 1536 + t * 16, g_wOffB + kt * 384 + t * 4);
        asm volatile("cp.async.commit_group;" ::: "memory");
    };

    float acc[3][4];
#pragma unroll
    for (int nt = 0; nt < 3; nt++)
#pragma unroll
        for (int r = 0; r < 4; r++) acc[nt][r] = 0.f;

    auto compute = [&](int s) {
        const uint32_t Ab = Ab0 + s * 4096;
        const uint32_t Bb = Bb0 + s * 1536;
#pragma unroll
        for (int k16 = 0; k16 < 2; k16++) {
            uint32_t a[4];
            {
                int mr = wm * 16;
                int tt = lane >> 3, r = lane & 7;
                int mrow = mr + ((tt & 1) << 3) + r;
                int rp2 = mrow >> 1;
                int cc = ((mrow & 1) << 2) + (k16 << 1) + (tt >> 1);
                uint32_t addr = Ab + rp2 * 128 + ((cc ^ (rp2 & 7)) << 4);
                asm volatile(
                    "ldmatrix.sync.aligned.m8n8.x4.shared.b16 {%0,%1,%2,%3}, [%4];"
                    : "=r"(a[0]), "=r"(a[1]), "=r"(a[2]), "=r"(a[3])
                    : "r"(addr));
            }
#pragma unroll
            for (int nt = 0; nt < 3; nt++) {
                uint32_t b0, b1;
                uint32_t addr = Bb + ((k16 * 3 + nt) * 64 + lane * 2) * 4;
                asm volatile("ld.shared.v2.u32 {%0,%1}, [%2];"
                             : "=r"(b0), "=r"(b1) : "r"(addr));
                mma_f16(acc[nt], a, b0, b1);
            }
        }
    };

    issue(0, 0);
    issue(1, 1);
    asm volatile("cp.async.wait_group 1;" ::: "memory");
    __syncthreads();

    for (int kt = 0; kt < NCHUNK; kt++) {
        compute(kt % 3);
        if (kt + 2 < NCHUNK) {
            issue(kt + 2, (kt + 2) % 3);
            asm volatile("cp.async.wait_group 1;" ::: "memory");
        } else {
            asm volatile("cp.async.wait_group 0;" ::: "memory");
        }
        __syncthreads();
    }

#pragma unroll
    for (int nt = 0; nt < 3; nt++) {
        int k = nt * 4 + tg;
        if (k < 9) {
            float by0 = b_off[2 * k];
            float by1 = b_off[2 * k + 1];
            int hw0 = (m0 & 4095) + wm * 16 + g;
            make_tab(b, hw0,     k, acc[nt][0] + by0, acc[nt][1] + by1);
            make_tab(b, hw0 + 8, k, acc[nt][2] + by0, acc[nt][3] + by1);
        }
    }
}

// ---------------- kernel: pipelined channel-vector gather ------------------
// warp = one pixel m; 9 taps software-pipelined 2 deep.
__global__ void __launch_bounds__(256) gather_A_kernel() {
    const int lane = threadIdx.x & 31;
    const int wid  = threadIdx.x >> 5;
    const int m = (blockIdx.x << 3) + wid;
    const int b = m >> 12;
    const __half* basep = g_xTp + (size_t)b * PP * CI;
    __half* dstm = g_A + (size_t)m * KD + lane * 8;

    ushort4 gi = g_tidx[m];
    uint4 wq   = g_tw2[m];
    uint4 a0 = __ldg((const uint4*)(basep + (int)gi.x * CI) + lane);
    uint4 a1 = __ldg((const uint4*)(basep + (int)gi.y * CI) + lane);
    uint4 a2 = __ldg((const uint4*)(basep + (int)gi.z * CI) + lane);
    uint4 a3 = __ldg((const uint4*)(basep + (int)gi.w * CI) + lane);

#pragma unroll
    for (int tap = 0; tap < 9; tap++) {
        uint4 n0, n1, n2, n3, wqn;
        if (tap < 8) {
            int idx = ((tap + 1) << 14) + m;
            ushort4 gin = g_tidx[idx];
            wqn = g_tw2[idx];
            n0 = __ldg((const uint4*)(basep + (int)gin.x * CI) + lane);
            n1 = __ldg((const uint4*)(basep + (int)gin.y * CI) + lane);
            n2 = __ldg((const uint4*)(basep + (int)gin.z * CI) + lane);
            n3 = __ldg((const uint4*)(basep + (int)gin.w * CI) + lane);
        }
        __half2 w0 = *(__half2*)&wq.x, w1 = *(__half2*)&wq.y;
        __half2 w2 = *(__half2*)&wq.z, w3 = *(__half2*)&wq.w;
        uint4 o;
        o.x = h2dot(a0.x, a1.x, a2.x, a3.x, w0, w1, w2, w3);
        o.y = h2dot(a0.y, a1.y, a2.y, a3.y, w0, w1, w2, w3);
        o.z = h2dot(a0.z, a1.z, a2.z, a3.z, w0, w1, w2, w3);
        o.w = h2dot(a0.w, a1.w, a2.w, a3.w, w0, w1, w2, w3);
        *(uint4*)(dstm + tap * 256) = o;
        if (tap < 8) {
            a0 = n0; a1 = n1; a2 = n2; a3 = n3; wq = wqn;
        }
    }
}

// ---------------- kernel: pipelined fp16 HMMA GEMM (KC=64) -----------------
#define ST_A 16384
#define ST_B 16384
#define OFF_A 0
#define OFF_B (3 * ST_A)
#define SMEM_GEMM (3 * ST_A + 3 * ST_B)     // 98304

__global__ void __launch_bounds__(256, 2)
gemm_main() {
    extern __shared__ char smem[];
    const uint32_t sb = smem_u32(smem);
    const int tid  = threadIdx.x;
    const int lane = tid & 31;
    const int wid  = tid >> 5;
    const int g  = lane >> 2;
    const int tg = lane & 3;
    const int wm = wid & 3;
    const int wn = wid >> 2;
    const int m0 = blockIdx.x << 7;
    const int by = blockIdx.y;
    const int b  = m0 >> 12;

    const int cm   = tid & 127;
    const int ckl0 = tid >> 7;

    auto issue = [&](int kt, int s) {
        const __half* arow = g_A + (size_t)(m0 + cm) * KD + kt * 64;
#pragma unroll
        for (int sub = 0; sub < 2; sub++) {
#pragma unroll
            for (int q = 0; q < 2; q++) {
                int ckl = ckl0 + q * 2;
                uint32_t dstA = (uint32_t)(sub * 8192 + (cm >> 1) * 128
                             + (((((cm & 1) << 2) + ckl) ^ ((cm >> 1) & 7)) << 4));
                cp_async16(sb + OFF_A + s * ST_A + dstA, arow + sub * 32 + ckl * 8);
            }
        }
        const float4* wb4 = (const float4*)g_wB;
#pragma unroll
        for (int r = 0; r < 4; r++) {
            int idx = r * 256 + tid;
            int sub = idx >> 9;
            int i2  = idx & 511;
            int k16 = i2 >> 8;
            int npl = (i2 >> 5) & 7;
            int ln  = i2 & 31;
            cp_async16(sb + OFF_B + s * ST_B + idx * 16,
                       wb4 + (size_t)(2 * kt + sub) * 1024 + k16 * 512
                           + (8 * by + npl) * 32 + ln);
        }
        asm volatile("cp.async.commit_group;" ::: "memory");
    };

    float acc[2][8][4];
#pragma unroll
    for (int mt = 0; mt < 2; mt++)
#pragma unroll
        for (int nt = 0; nt < 8; nt++)
#pragma unroll
            for (int r = 0; r < 4; r++) acc[mt][nt][r] = 0.f;

    auto compute = [&](int s) {
#pragma unroll
        for (int k32 = 0; k32 < 2; k32++) {
            const uint32_t Ab = sb + OFF_A + s * ST_A + k32 * 8192;
            const uint32_t Bb = sb + OFF_B + s * ST_B + k32 * 8192;
#pragma unroll
            for (int k16 = 0; k16 < 2; k16++) {
                uint32_t a[2][4];
#pragma unroll
                for (int mt = 0; mt < 2; mt++) {
                    int mr = wm * 32 + mt * 16;
                    int t = lane >> 3, r = lane & 7;
                    int mrow = mr + ((t & 1) << 3) + r;
                    int rp = mrow >> 1;
                    int cc = ((mrow & 1) << 2) + (k16 << 1) + (t >> 1);
                    uint32_t addr = Ab + rp * 128 + ((cc ^ (rp & 7)) << 4);
                    asm volatile(
                        "ldmatrix.sync.aligned.m8n8.x4.shared.b16 {%0,%1,%2,%3}, [%4];"
                        : "=r"(a[mt][0]), "=r"(a[mt][1]), "=r"(a[mt][2]), "=r"(a[mt][3])
                        : "r"(addr));
                }
#pragma unroll
                for (int j = 0; j < 4; j++) {
                    uint32_t b0, b1, b2, b3;
                    uint32_t addr = Bb + (((k16 * 8) + wn * 4 + j) * 32 + lane) * 16;
                    asm volatile("ld.shared.v4.u32 {%0,%1,%2,%3}, [%4];"
                                 : "=r"(b0), "=r"(b1), "=r"(b2), "=r"(b3) : "r"(addr));
                    mma_f16(acc[0][2 * j],     a[0], b0, b1);
                    mma_f16(acc[1][2 * j],     a[1], b0, b1);
                    mma_f16(acc[0][2 * j + 1], a[0], b2, b3);
                    mma_f16(acc[1][2 * j + 1], a[1], b2, b3);
                }
            }
        }
    };

    issue(0, 0);
    issue(1, 1);
    asm volatile("cp.async.wait_group 1;" ::: "memory");
    __syncthreads();

    for (int kt = 0; kt < NKT2; kt++) {
        compute(kt % 3);
        if (kt + 2 < NKT2) {
            issue(kt + 2, (kt + 2) % 3);
            asm volatile("cp.async.wait_group 1;" ::: "memory");
        } else {
            asm volatile("cp.async.wait_group 0;" ::: "memory");
        }
        __syncthreads();
    }

    const int hwb = (m0 & 4095);
#pragma unroll
    for (int nt = 0; nt < 8; nt++) {
        int n = by * 128 + wn * 64 + nt * 8 + 2 * tg;
        float* p0 = g_raw + ((size_t)(b * CO + n) << 12);
        float* p1 = p0 + HW;
        float s0 = 0.f, q0 = 0.f, s1 = 0.f, q1 = 0.f;
#pragma unroll
        for (int mt = 0; mt < 2; mt++) {
            int hw0 = hwb + wm * 32 + mt * 16 + g;
            float d0 = acc[mt][nt][0], d1 = acc[mt][nt][1];
            float d2 = acc[mt][nt][2], d3 = acc[mt][nt][3];
            p0[hw0]     = d0;
            p1[hw0]     = d1;
            p0[hw0 + 8] = d2;
            p1[hw0 + 8] = d3;
            s0 += d0 + d2;  q0 += d0 * d0 + d2 * d2;
            s1 += d1 + d3;  q1 += d1 * d1 + d3 * d3;
        }
#pragma unroll
        for (int o = 4; o < 32; o <<= 1) {
            s0 += __shfl_xor_sync(0xFFFFFFFF, s0, o);
            q0 += __shfl_xor_sync(0xFFFFFFFF, q0, o);
            s1 += __shfl_xor_sync(0xFFFFFFFF, s1, o);
            q1 += __shfl_xor_sync(0xFFFFFFFF, q1, o);
        }
        if (lane < 4) {
            atomicAdd(&g_sum[n], s0);
            atomicAdd(&g_sum2[n], q0);
            atomicAdd(&g_sum[n + 1], s1);
            atomicAdd(&g_sum2[n + 1], q1);
        }
    }
}

// ---------------- BN finalize + apply (fused) -------------------------------
__global__ void bn_apply(float* __restrict__ out,
                         const float* __restrict__ gamma,
                         const float* __restrict__ beta) {
    __shared__ float ssc[256], ssh[256];
    int t = threadIdx.x;
    {
        float mean = g_sum[t] * (1.f / 16384.f);
        float var  = g_sum2[t] * (1.f / 16384.f) - mean * mean;
        float inv  = gamma[t] * rsqrtf(var + 1e-5f);
        ssc[t] = inv;
        ssh[t] = beta[t] - mean * inv;
    }
    __syncthreads();
    int base = blockIdx.x * 1024;
#pragma unroll
    for (int r = 0; r < 4; r++) {
        int i = base + r * 256 + t;
        int o = (i >> 10) & 255;
        float4 v = ((const float4*)g_raw)[i];
        float sc = ssc[o], sf = ssh[o];
        float4 q;
        q.x = fmaxf(v.x * sc + sf, 0.f);
        q.y = fmaxf(v.y * sc + sf, 0.f);
        q.z = fmaxf(v.z * sc + sf, 0.f);
        q.w = fmaxf(v.w * sc + sf, 0.f);
        ((float4*)out)[i] = q;
    }
}

// ---------------- launch ----------------
extern "C" void kernel_launch(void* const* d_in, const int* in_sizes, int n_in,
                              void* d_out, int out_size) {
    const float* x      = (const float*)d_in[0];
    const float* w_off  = (const float*)d_in[1];
    const float* b_off  = (const float*)d_in[2];
    const float* w_conv = (const float*)d_in[3];
    const float* gamma  = (const float*)d_in[4];
    const float* beta   = (const float*)d_in[5];
    float* out = (float*)d_out;

    cudaFuncSetAttribute(gemm_main,
                         cudaFuncAttributeMaxDynamicSharedMemorySize, SMEM_GEMM);

    prep_all<<<NB_PREP, 256>>>(x, w_conv, w_off);
    offset_gemm<<<MTOT / 64, 128>>>(b_off);
    gather_A_kernel<<<MTOT / 8, 256>>>();
    gemm_main<<<dim3(MTOT / 128, 2), 256, SMEM_GEMM>>>();
    bn_apply<<<(BB * CO * HW / 4) / 1024, 256>>>(out, gamma, beta);
}

// round 12
// speedup vs baseline: 1.7423x; 1.0303x over previous
#include <cuda_runtime.h>
#include <cuda_fp16.h>
#include <cstdint>

#define BB 4
#define CI 256
#define CO 256
#define HH 64
#define WW 64
#define HW 4096
#define KD 2304          // CI * 9
#define MTOT 16384
#define NCHUNK 72        // KD / 32  (B packing granularity)
#define NKT2 36          // KD / 64  (gemm main-loop chunks)
#define PP 4356          // 66*66 padded pixels

// ---------------- scratch ----------------
__device__ __align__(16) uint32_t g_wB[NCHUNK * 4096];     // frag-ordered fp16 B (main, tap-major k)
__device__ __align__(16) uint32_t g_wOffB[NCHUNK * 384];   // frag-ordered fp16 B (offset)
__device__ __align__(16) __half g_A[(size_t)MTOT * KD];    // sampled A fp16, [m][2304]
__device__ __align__(16) __half g_xTp[BB * PP * CI];       // fp16 x, padded transposed (hw, c)
__device__ __align__(16) ushort4 g_tidx[9 * MTOT];         // corner PADDED row indices
__device__ __align__(16) uint4   g_tw2[9 * MTOT];          // corner weights as 4x half2
__device__ __align__(16) float g_raw[BB * CO * HW];
__device__ float g_sum[CO];
__device__ float g_sum2[CO];

// ---------------- helpers ----------------
__device__ __forceinline__ uint32_t smem_u32(const void* p) {
    uint32_t a;
    asm("{ .reg .u64 t; cvta.to.shared.u64 t, %1; cvt.u32.u64 %0, t; }" : "=r"(a) : "l"(p));
    return a;
}
__device__ __forceinline__ uint32_t pack_h2(float lo, float hi) {
    __half2 h = __floats2half2_rn(lo, hi);
    return *(uint32_t*)&h;
}
__device__ __forceinline__ void mma_f16(float* d, const uint32_t* a,
                                        uint32_t b0, uint32_t b1) {
    asm volatile(
        "mma.sync.aligned.m16n8k16.row.col.f32.f16.f16.f32 "
        "{%0,%1,%2,%3}, {%4,%5,%6,%7}, {%8,%9}, {%0,%1,%2,%3};"
        : "+f"(d[0]), "+f"(d[1]), "+f"(d[2]), "+f"(d[3])
        : "r"(a[0]), "r"(a[1]), "r"(a[2]), "r"(a[3]), "r"(b0), "r"(b1));
}
__device__ __forceinline__ void cp_async16(uint32_t saddr, const void* gaddr) {
    asm volatile("cp.async.cg.shared.global [%0], [%1], 16;" :: "r"(saddr), "l"(gaddr));
}
__device__ __forceinline__ uint32_t h2dot(uint32_t c0, uint32_t c1, uint32_t c2, uint32_t c3,
                                          __half2 w0, __half2 w1, __half2 w2, __half2 w3) {
    __half2 r = __hmul2(w0, *(__half2*)&c0);
    r = __hfma2(w1, *(__half2*)&c1, r);
    r = __hfma2(w2, *(__half2*)&c2, r);
    r = __hfma2(w3, *(__half2*)&c3, r);
    return *(uint32_t*)&r;
}

// bilinear table construction for one (pixel, tap)
__device__ __forceinline__ void make_tab(int b, int hw, int k, float offy, float offx) {
    int h = hw >> 6, w = hw & 63;
    int k3 = k / 3;
    float py = (float)(h + k3 - 1) + offy;
    float px = (float)(w + (k - k3 * 3) - 1) + offx;
    float fy0 = floorf(py), fx0 = floorf(px);
    float wy1 = py - fy0, wx1 = px - fx0;
    float wy0 = 1.f - wy1, wx0 = 1.f - wx1;
    int iy0 = (int)fy0, ix0 = (int)fx0;
    int iy1 = iy0 + 1, ix1 = ix0 + 1;
    float vy0 = (iy0 >= 0 && iy0 < HH) ? 1.f : 0.f;
    float vy1 = (iy1 >= 0 && iy1 < HH) ? 1.f : 0.f;
    float vx0 = (ix0 >= 0 && ix0 < WW) ? 1.f : 0.f;
    float vx1 = (ix1 >= 0 && ix1 < WW) ? 1.f : 0.f;
    int cy0 = min(max(iy0, 0), HH - 1), cy1 = min(max(iy1, 0), HH - 1);
    int cx0 = min(max(ix0, 0), WW - 1), cx1 = min(max(ix1, 0), WW - 1);
    ushort4 gi;
    gi.x = (unsigned short)((cy0 + 1) * 66 + cx0 + 1);
    gi.y = (unsigned short)((cy0 + 1) * 66 + cx1 + 1);
    gi.z = (unsigned short)((cy1 + 1) * 66 + cx0 + 1);
    gi.w = (unsigned short)((cy1 + 1) * 66 + cx1 + 1);
    int idx = (k << 14) + (b << 12) + hw;
    g_tidx[idx] = gi;
    float w00 = wy0 * wx0 * vy0 * vx0;
    float w01 = wy0 * wx1 * vy0 * vx1;
    float w10 = wy1 * wx0 * vy1 * vx0;
    float w11 = wy1 * wx1 * vy1 * vx1;
    uint4 wq;
    wq.x = pack_h2(w00, w00);
    wq.y = pack_h2(w01, w01);
    wq.z = pack_h2(w10, w10);
    wq.w = pack_h2(w11, w11);
    g_tw2[idx] = wq;
}

// ---------------- kernel: unified prep (xhT + wB + pad + wOffB + stats) ----
#define N_WB   (NCHUNK * 4096)
#define N_PAD  (BB * 260 * 32)
#define N_WOFF (NCHUNK * 384)
#define N_MISC (N_WB + N_PAD + N_WOFF + 256)    // 356096 = 1391*256
#define NB_XHT (BB * HH * 4)                    // 1024 transpose blocks
#define NB_PREP (NB_XHT + N_MISC / 256)         // 2415

__global__ void prep_all(const float* __restrict__ x,
                         const float* __restrict__ w_conv,
                         const float* __restrict__ w_off) {
    __shared__ float tile[64][65];
    int blk = blockIdx.x;
    int t = threadIdx.x;
    if (blk < NB_XHT) {
        int bh = blk & 255;
        int c0 = (blk >> 8) * 64;
        int b = bh >> 6, h = bh & 63;
        int ci = t >> 6, w = t & 63;
#pragma unroll
        for (int rep = 0; rep < 16; rep++) {
            int c = c0 + ci + rep * 4;
            tile[ci + rep * 4][w] = x[((size_t)(b * CI + c) << 12) + h * 64 + w];
        }
        __syncthreads();
#pragma unroll
        for (int rep = 0; rep < 2; rep++) {
            int e = t + rep * 256;
            int w2 = e & 63, q = e >> 6;
            __half hv[8];
#pragma unroll
            for (int j = 0; j < 8; j++) hv[j] = __float2half(tile[q * 8 + j][w2]);
            size_t dst = ((size_t)b * PP + (h + 1) * 66 + (w2 + 1)) * CI + c0 + q * 8;
            *(uint4*)(g_xTp + dst) = *(uint4*)hv;
        }
        return;
    }
    int idx = (blk - NB_XHT) * 256 + t;
    if (idx < N_WB) {
        int kt = idx >> 12;
        int r  = idx & 4095;
        int k16  = r >> 11;
        int np   = (r >> 7) & 15;
        int lane = (r >> 2) & 31;
        int w    = r & 3;
        int g = lane >> 2, tg = lane & 3;
        int nt = np * 2 + (w >> 1);
        int h  = w & 1;
        int n  = nt * 8 + g;
        int ck = kt * 32 + k16 * 16 + h * 8 + 2 * tg;   // tap-major k index
        int tap = ck >> 8;
        int c   = ck & 255;
        g_wB[idx] = pack_h2(w_conv[n * KD + c * 9 + tap],
                            w_conv[n * KD + (c + 1) * 9 + tap]);
        return;
    }
    idx -= N_WB;
    if (idx < N_PAD) {
        int q = idx & 31;
        int r = (idx >> 5) % 260;
        int b = idx / (260 * 32);
        int row;
        if (r < 66)       row = r;
        else if (r < 132) row = 65 * 66 + (r - 66);
        else if (r < 196) row = (r - 132 + 1) * 66;
        else              row = (r - 196 + 1) * 66 + 65;
        ((uint4*)(g_xTp + ((size_t)b * PP + row) * CI))[q] = make_uint4(0, 0, 0, 0);
        return;
    }
    idx -= N_PAD;
    if (idx < N_WOFF) {
        int kt = idx / 384;
        int r  = idx - kt * 384;
        int k16  = r / 192;
        int nt   = (r / 64) % 3;
        int lane = (r >> 1) & 31;
        int h    = r & 1;
        int g = lane >> 2, tg = lane & 3;
        int n = nt * 8 + g;
        int tap = kt >> 3;
        int c = (kt & 7) * 32 + k16 * 16 + h * 8 + 2 * tg;
        uint32_t val = 0;
        if (n < 18)
            val = pack_h2(w_off[n * KD + c * 9 + tap], w_off[n * KD + (c + 1) * 9 + tap]);
        g_wOffB[idx] = val;
        return;
    }
    idx -= N_WOFF;
    if (idx < 256) {
        g_sum[idx] = 0.f;
        g_sum2[idx] = 0.f;
    }
}

// ---------------- kernel: offset conv GEMM + fused bilinear tables ---------
__global__ void __launch_bounds__(128)
offset_gemm(const float* __restrict__ b_off) {
    __shared__ __align__(16) char As[3 * 4096];
    __shared__ __align__(16) char Bs[3 * 1536];
    const uint32_t Ab0 = smem_u32(As);
    const uint32_t Bb0 = smem_u32(Bs);
    const int t = threadIdx.x;
    const int lane = t & 31;
    const int wm = t >> 5;
    const int g = lane >> 2;
    const int tg = lane & 3;
    const int m0 = blockIdx.x << 6;
    const int b  = m0 >> 12;

    const int ar = t & 63;
    const int part = t >> 6;
    const int hw_a = (m0 + ar) & 4095;
    const int prow = ((hw_a >> 6) + 1) * 66 + (hw_a & 63) + 1;
    const __half* arow = g_xTp + ((size_t)b * PP + prow) * CI;
    const int rp = ar >> 1;
    const uint32_t dstA_base = rp * 128;

    auto issue = [&](int kt, int s) {
        int tap = kt >> 3;
        int shift = (tap / 3 - 1) * 66 + (tap % 3 - 1);
        const __half* src = arow + (size_t)shift * CI + (kt & 7) * 32;
#pragma unroll
        for (int qq = 0; qq < 2; qq++) {
            int q = part * 2 + qq;
            uint32_t cc = ((ar & 1) << 2) + q;
            cp_async16(Ab0 + s * 4096 + dstA_base + ((cc ^ (rp & 7)) << 4), src + q * 8);
        }
        if (t < 96)
            cp_async16(Bb0 + s * 1536 + t * 16, g_wOffB + kt * 384 + t * 4);
        asm volatile("cp.async.commit_group;" ::: "memory");
    };

    float acc[3][4];
#pragma unroll
    for (int nt = 0; nt < 3; nt++)
#pragma unroll
        for (int r = 0; r < 4; r++) acc[nt][r] = 0.f;

    auto compute = [&](int s) {
        const uint32_t Ab = Ab0 + s * 4096;
        const uint32_t Bb = Bb0 + s * 1536;
#pragma unroll
        for (int k16 = 0; k16 < 2; k16++) {
            uint32_t a[4];
            {
                int mr = wm * 16;
                int tt = lane >> 3, r = lane & 7;
                int mrow = mr + ((tt & 1) << 3) + r;
                int rp2 = mrow >> 1;
                int cc = ((mrow & 1) << 2) + (k16 << 1) + (tt >> 1);
                uint32_t addr = Ab + rp2 * 128 + ((cc ^ (rp2 & 7)) << 4);
                asm volatile(
                    "ldmatrix.sync.aligned.m8n8.x4.shared.b16 {%0,%1,%2,%3}, [%4];"
                    : "=r"(a[0]), "=r"(a[1]), "=r"(a[2]), "=r"(a[3])
                    : "r"(addr));
            }
#pragma unroll
            for (int nt = 0; nt < 3; nt++) {
                uint32_t b0, b1;
                uint32_t addr = Bb + ((k16 * 3 + nt) * 64 + lane * 2) * 4;
                asm volatile("ld.shared.v2.u32 {%0,%1}, [%2];"
                             : "=r"(b0), "=r"(b1) : "r"(addr));
                mma_f16(acc[nt], a, b0, b1);
            }
        }
    };

    issue(0, 0);
    issue(1, 1);
    asm volatile("cp.async.wait_group 1;" ::: "memory");
    __syncthreads();

    // 72 iterations, unrolled by 3 for static stage indices
#pragma unroll 1
    for (int it = 0; it < NCHUNK / 3; it++) {
        int kt = it * 3;
        compute(0);
        if (kt + 2 < NCHUNK) {
            issue(kt + 2, 2);
            asm volatile("cp.async.wait_group 1;" ::: "memory");
        } else {
            asm volatile("cp.async.wait_group 0;" ::: "memory");
        }
        __syncthreads();
        compute(1);
        if (kt + 3 < NCHUNK) {
            issue(kt + 3, 0);
            asm volatile("cp.async.wait_group 1;" ::: "memory");
        } else {
            asm volatile("cp.async.wait_group 0;" ::: "memory");
        }
        __syncthreads();
        compute(2);
        if (kt + 4 < NCHUNK) {
            issue(kt + 4, 1);
            asm volatile("cp.async.wait_group 1;" ::: "memory");
        } else {
            asm volatile("cp.async.wait_group 0;" ::: "memory");
        }
        __syncthreads();
    }

#pragma unroll
    for (int nt = 0; nt < 3; nt++) {
        int k = nt * 4 + tg;
        if (k < 9) {
            float by0 = b_off[2 * k];
            float by1 = b_off[2 * k + 1];
            int hw0 = (m0 & 4095) + wm * 16 + g;
            make_tab(b, hw0,     k, acc[nt][0] + by0, acc[nt][1] + by1);
            make_tab(b, hw0 + 8, k, acc[nt][2] + by0, acc[nt][3] + by1);
        }
    }
}

// ---------------- kernel: pipelined channel-vector gather ------------------
__global__ void __launch_bounds__(256) gather_A_kernel() {
    const int lane = threadIdx.x & 31;
    const int wid  = threadIdx.x >> 5;
    const int m = (blockIdx.x << 3) + wid;
    const int b = m >> 12;
    const __half* basep = g_xTp + (size_t)b * PP * CI;
    __half* dstm = g_A + (size_t)m * KD + lane * 8;

    ushort4 gi = g_tidx[m];
    uint4 wq   = g_tw2[m];
    uint4 a0 = __ldg((const uint4*)(basep + (int)gi.x * CI) + lane);
    uint4 a1 = __ldg((const uint4*)(basep + (int)gi.y * CI) + lane);
    uint4 a2 = __ldg((const uint4*)(basep + (int)gi.z * CI) + lane);
    uint4 a3 = __ldg((const uint4*)(basep + (int)gi.w * CI) + lane);

#pragma unroll
    for (int tap = 0; tap < 9; tap++) {
        uint4 n0, n1, n2, n3, wqn;
        if (tap < 8) {
            int idx = ((tap + 1) << 14) + m;
            ushort4 gin = g_tidx[idx];
            wqn = g_tw2[idx];
            n0 = __ldg((const uint4*)(basep + (int)gin.x * CI) + lane);
            n1 = __ldg((const uint4*)(basep + (int)gin.y * CI) + lane);
            n2 = __ldg((const uint4*)(basep + (int)gin.z * CI) + lane);
            n3 = __ldg((const uint4*)(basep + (int)gin.w * CI) + lane);
        }
        __half2 w0 = *(__half2*)&wq.x, w1 = *(__half2*)&wq.y;
        __half2 w2 = *(__half2*)&wq.z, w3 = *(__half2*)&wq.w;
        uint4 o;
        o.x = h2dot(a0.x, a1.x, a2.x, a3.x, w0, w1, w2, w3);
        o.y = h2dot(a0.y, a1.y, a2.y, a3.y, w0, w1, w2, w3);
        o.z = h2dot(a0.z, a1.z, a2.z, a3.z, w0, w1, w2, w3);
        o.w = h2dot(a0.w, a1.w, a2.w, a3.w, w0, w1, w2, w3);
        *(uint4*)(dstm + tap * 256) = o;
        if (tap < 8) {
            a0 = n0; a1 = n1; a2 = n2; a3 = n3; wq = wqn;
        }
    }
}

// ---------------- kernel: pipelined fp16 HMMA GEMM (KC=64) -----------------
#define ST_A 16384
#define ST_B 16384
#define OFF_A 0
#define OFF_B (3 * ST_A)
#define SMEM_GEMM (3 * ST_A + 3 * ST_B)     // 98304

__global__ void __launch_bounds__(256, 2)
gemm_main() {
    extern __shared__ char smem[];
    const uint32_t sb = smem_u32(smem);
    const int tid  = threadIdx.x;
    const int lane = tid & 31;
    const int wid  = tid >> 5;
    const int g  = lane >> 2;
    const int tg = lane & 3;
    const int wm = wid & 3;
    const int wn = wid >> 2;
    const int m0 = blockIdx.x << 7;
    const int by = blockIdx.y;
    const int b  = m0 >> 12;

    const int cm   = tid & 127;
    const int ckl0 = tid >> 7;

    auto issue = [&](int kt, int s) {
        const __half* arow = g_A + (size_t)(m0 + cm) * KD + kt * 64;
#pragma unroll
        for (int sub = 0; sub < 2; sub++) {
#pragma unroll
            for (int q = 0; q < 2; q++) {
                int ckl = ckl0 + q * 2;
                uint32_t dstA = (uint32_t)(sub * 8192 + (cm >> 1) * 128
                             + (((((cm & 1) << 2) + ckl) ^ ((cm >> 1) & 7)) << 4));
                cp_async16(sb + OFF_A + s * ST_A + dstA, arow + sub * 32 + ckl * 8);
            }
        }
        const float4* wb4 = (const float4*)g_wB;
#pragma unroll
        for (int r = 0; r < 4; r++) {
            int idx = r * 256 + tid;
            int sub = idx >> 9;
            int i2  = idx & 511;
            int k16 = i2 >> 8;
            int npl = (i2 >> 5) & 7;
            int ln  = i2 & 31;
            cp_async16(sb + OFF_B + s * ST_B + idx * 16,
                       wb4 + (size_t)(2 * kt + sub) * 1024 + k16 * 512
                           + (8 * by + npl) * 32 + ln);
        }
        asm volatile("cp.async.commit_group;" ::: "memory");
    };

    float acc[2][8][4];
#pragma unroll
    for (int mt = 0; mt < 2; mt++)
#pragma unroll
        for (int nt = 0; nt < 8; nt++)
#pragma unroll
            for (int r = 0; r < 4; r++) acc[mt][nt][r] = 0.f;

    auto compute = [&](int s) {
#pragma unroll
        for (int k32 = 0; k32 < 2; k32++) {
            const uint32_t Ab = sb + OFF_A + s * ST_A + k32 * 8192;
            const uint32_t Bb = sb + OFF_B + s * ST_B + k32 * 8192;
#pragma unroll
            for (int k16 = 0; k16 < 2; k16++) {
                uint32_t a[2][4];
#pragma unroll
                for (int mt = 0; mt < 2; mt++) {
                    int mr = wm * 32 + mt * 16;
                    int t = lane >> 3, r = lane & 7;
                    int mrow = mr + ((t & 1) << 3) + r;
                    int rp = mrow >> 1;
                    int cc = ((mrow & 1) << 2) + (k16 << 1) + (t >> 1);
                    uint32_t addr = Ab + rp * 128 + ((cc ^ (rp & 7)) << 4);
                    asm volatile(
                        "ldmatrix.sync.aligned.m8n8.x4.shared.b16 {%0,%1,%2,%3}, [%4];"
                        : "=r"(a[mt][0]), "=r"(a[mt][1]), "=r"(a[mt][2]), "=r"(a[mt][3])
                        : "r"(addr));
                }
#pragma unroll
                for (int j = 0; j < 4; j++) {
                    uint32_t b0, b1, b2, b3;
                    uint32_t addr = Bb + (((k16 * 8) + wn * 4 + j) * 32 + lane) * 16;
                    asm volatile("ld.shared.v4.u32 {%0,%1,%2,%3}, [%4];"
                                 : "=r"(b0), "=r"(b1), "=r"(b2), "=r"(b3) : "r"(addr));
                    mma_f16(acc[0][2 * j],     a[0], b0, b1);
                    mma_f16(acc[1][2 * j],     a[1], b0, b1);
                    mma_f16(acc[0][2 * j + 1], a[0], b2, b3);
                    mma_f16(acc[1][2 * j + 1], a[1], b2, b3);
                }
            }
        }
    };

    issue(0, 0);
    issue(1, 1);
    asm volatile("cp.async.wait_group 1;" ::: "memory");
    __syncthreads();

    // 36 iterations, unrolled by 3 for static stage indices
#pragma unroll 1
    for (int it = 0; it < NKT2 / 3; it++) {
        int kt = it * 3;
        compute(0);
        if (kt + 2 < NKT2) {
            issue(kt + 2, 2);
            asm volatile("cp.async.wait_group 1;" ::: "memory");
        } else {
            asm volatile("cp.async.wait_group 0;" ::: "memory");
        }
        __syncthreads();
        compute(1);
        if (kt + 3 < NKT2) {
            issue(kt + 3, 0);
            asm volatile("cp.async.wait_group 1;" ::: "memory");
        } else {
            asm volatile("cp.async.wait_group 0;" ::: "memory");
        }
        __syncthreads();
        compute(2);
        if (kt + 4 < NKT2) {
            issue(kt + 4, 1);
            asm volatile("cp.async.wait_group 1;" ::: "memory");
        } else {
            asm volatile("cp.async.wait_group 0;" ::: "memory");
        }
        __syncthreads();
    }

    const int hwb = (m0 & 4095);
#pragma unroll
    for (int nt = 0; nt < 8; nt++) {
        int n = by * 128 + wn * 64 + nt * 8 + 2 * tg;
        float* p0 = g_raw + ((size_t)(b * CO + n) << 12);
        float* p1 = p0 + HW;
        float s0 = 0.f, q0 = 0.f, s1 = 0.f, q1 = 0.f;
#pragma unroll
        for (int mt = 0; mt < 2; mt++) {
            int hw0 = hwb + wm * 32 + mt * 16 + g;
            float d0 = acc[mt][nt][0], d1 = acc[mt][nt][1];
            float d2 = acc[mt][nt][2], d3 = acc[mt][nt][3];
            p0[hw0]     = d0;
            p1[hw0]     = d1;
            p0[hw0 + 8] = d2;
            p1[hw0 + 8] = d3;
            s0 += d0 + d2;  q0 += d0 * d0 + d2 * d2;
            s1 += d1 + d3;  q1 += d1 * d1 + d3 * d3;
        }
#pragma unroll
        for (int o = 4; o < 32; o <<= 1) {
            s0 += __shfl_xor_sync(0xFFFFFFFF, s0, o);
            q0 += __shfl_xor_sync(0xFFFFFFFF, q0, o);
            s1 += __shfl_xor_sync(0xFFFFFFFF, s1, o);
            q1 += __shfl_xor_sync(0xFFFFFFFF, q1, o);
        }
        if (lane < 4) {
            atomicAdd(&g_sum[n], s0);
            atomicAdd(&g_sum2[n], q0);
            atomicAdd(&g_sum[n + 1], s1);
            atomicAdd(&g_sum2[n + 1], q1);
        }
    }
}

// ---------------- BN finalize + apply (fused) -------------------------------
__global__ void bn_apply(float* __restrict__ out,
                         const float* __restrict__ gamma,
                         const float* __restrict__ beta) {
    __shared__ float ssc[256], ssh[256];
    int t = threadIdx.x;
    {
        float mean = g_sum[t] * (1.f / 16384.f);
        float var  = g_sum2[t] * (1.f / 16384.f) - mean * mean;
        float inv  = gamma[t] * rsqrtf(var + 1e-5f);
        ssc[t] = inv;
        ssh[t] = beta[t] - mean * inv;
    }
    __syncthreads();
    int base = blockIdx.x * 1024;
#pragma unroll
    for (int r = 0; r < 4; r++) {
        int i = base + r * 256 + t;
        int o = (i >> 10) & 255;
        float4 v = ((const float4*)g_raw)[i];
        float sc = ssc[o], sf = ssh[o];
        float4 q;
        q.x = fmaxf(v.x * sc + sf, 0.f);
        q.y = fmaxf(v.y * sc + sf, 0.f);
        q.z = fmaxf(v.z * sc + sf, 0.f);
        q.w = fmaxf(v.w * sc + sf, 0.f);
        ((float4*)out)[i] = q;
    }
}

// ---------------- launch ----------------
extern "C" void kernel_launch(void* const* d_in, const int* in_sizes, int n_in,
                              void* d_out, int out_size) {
    const float* x      = (const float*)d_in[0];
    const float* w_off  = (const float*)d_in[1];
    const float* b_off  = (const float*)d_in[2];
    const float* w_conv = (const float*)d_in[3];
    const float* gamma  = (const float*)d_in[4];
    const float* beta   = (const float*)d_in[5];
    float* out = (float*)d_out;

    cudaFuncSetAttribute(gemm_main,
                         cudaFuncAttributeMaxDynamicSharedMemorySize, SMEM_GEMM);

    prep_all<<<NB_PREP, 256>>>(x, w_conv, w_off);
    offset_gemm<<<MTOT / 64, 128>>>(b_off);
    gather_A_kernel<<<MTOT / 8, 256>>>();
    gemm_main<<<dim3(MTOT / 128, 2), 256, SMEM_GEMM>>>();
    bn_apply<<<(BB * CO * HW / 4) / 1024, 256>>>(out, gamma, beta);
}